// round 13
// baseline (speedup 1.0000x reference)
#include <cuda_runtime.h>
#include <cuda_bf16.h>
#include <cstdint>
#include <cstddef>

// ---------------------------------------------------------------------------
// Problem constants
// ---------------------------------------------------------------------------
static constexpr int BATCH   = 2;
static constexpr int SEQ     = 2048;
static constexpr int HID     = 4096;
static constexpr int NHEADS  = 32;
static constexpr int HDIM    = 128;
static constexpr int QRANK   = 1536;
static constexpr int KVRANK  = 512;
static constexpr int TOKENS  = BATCH * SEQ;            // 4096
static constexpr int MODEL   = NHEADS * HDIM;          // 4096
static constexpr int NQKVA   = QRANK + KVRANK;         // 2048
static constexpr int NKV     = 2 * MODEL;              // 8192
static constexpr float SM_SCALE = 0.08838834764831845f; // 1/sqrt(128)

// ---------------------------------------------------------------------------
// Scratch (static device allocations; no cudaMalloc anywhere)
// ---------------------------------------------------------------------------
__device__ float g_qc  [(size_t)TOKENS * QRANK];       // tf32 bits
__device__ float g_q   [(size_t)TOKENS * MODEL];       // tf32 bits, pre-scaled
__device__ float g_kv  [(size_t)TOKENS * NKV];         // tf32 bits: K cols 0-4095, V cols 4096-8191
__device__ float g_ao  [(size_t)TOKENS * MODEL];       // tf32 bits
__device__ float g_xt  [(size_t)TOKENS * HID];         // tf32 bits
__device__ float g_ckvt[(size_t)TOKENS * KVRANK];      // tf32 bits
__device__ float g_wqkva[(size_t)HID   * NQKVA];       // [wqa | wkva], tf32 bits
__device__ float g_wqb [(size_t)QRANK  * MODEL];       // tf32 bits
__device__ float g_wkv8[(size_t)KVRANK * NKV];         // [wkb | wvb], tf32 bits
__device__ float g_wo  [(size_t)MODEL  * HID];         // tf32 bits

// ---------------------------------------------------------------------------
// Helpers
// ---------------------------------------------------------------------------
__device__ __forceinline__ uint32_t f2tf32(float x) {
    uint32_t r;
    asm("cvt.rna.tf32.f32 %0, %1;" : "=r"(r) : "f"(x));
    return r;
}
__device__ __forceinline__ uint32_t smem_u32(const void* p) {
    uint32_t a;
    asm("{ .reg .u64 t; cvta.to.shared.u64 t, %1; cvt.u32.u64 %0, t; }"
        : "=r"(a) : "l"(p));
    return a;
}
__device__ __forceinline__ void cp_async16(uint32_t s, const void* g) {
    asm volatile("cp.async.cg.shared.global [%0], [%1], 16;" :: "r"(s), "l"(g));
}
#define CP_COMMIT() asm volatile("cp.async.commit_group;" ::: "memory")
#define CP_WAIT1()  asm volatile("cp.async.wait_group 1;" ::: "memory")

__device__ __forceinline__ void mma_tf32(float c[4], const uint32_t a[4],
                                         const uint32_t b[2]) {
    asm volatile(
        "mma.sync.aligned.m16n8k8.row.col.f32.tf32.tf32.f32 "
        "{%0,%1,%2,%3}, {%4,%5,%6,%7}, {%8,%9}, {%0,%1,%2,%3};"
        : "+f"(c[0]), "+f"(c[1]), "+f"(c[2]), "+f"(c[3])
        : "r"(a[0]), "r"(a[1]), "r"(a[2]), "r"(a[3]), "r"(b[0]), "r"(b[1]));
}

// ---------------------------------------------------------------------------
// Fused tf32 conversion pre-pass: one launch handles all 7 segments.
// ---------------------------------------------------------------------------
struct CvtArgs {
    const float4* src[7];
    float*        dst[7];
};

__constant__ const int CVT_NIN4[7] = {1024, 384, 128, 1024, 1024, 1024, 1024};
__constant__ const int CVT_NOUT[7] = {HID, NQKVA, NQKVA, MODEL, NKV, NKV, HID};
__constant__ const int CVT_COFF[7] = {0, 0, QRANK, 0, 0, MODEL, 0};
static constexpr long CVT_N4[7] = {
    (long)TOKENS * HID / 4,     // X
    (long)HID * QRANK / 4,      // w_qa
    (long)HID * KVRANK / 4,     // w_kva
    (long)QRANK * MODEL / 4,    // w_qb
    (long)KVRANK * MODEL / 4,   // w_kb
    (long)KVRANK * MODEL / 4,   // w_vb
    (long)MODEL * HID / 4       // w_o
};
static constexpr long CVT_CUM0 = 0;
static constexpr long CVT_CUM1 = CVT_CUM0 + CVT_N4[0];
static constexpr long CVT_CUM2 = CVT_CUM1 + CVT_N4[1];
static constexpr long CVT_CUM3 = CVT_CUM2 + CVT_N4[2];
static constexpr long CVT_CUM4 = CVT_CUM3 + CVT_N4[3];
static constexpr long CVT_CUM5 = CVT_CUM4 + CVT_N4[4];
static constexpr long CVT_CUM6 = CVT_CUM5 + CVT_N4[5];
static constexpr long CVT_TOTAL = CVT_CUM6 + CVT_N4[6];
static constexpr int  CVT_BLOCKS = (int)(CVT_TOTAL / 256);

__global__ __launch_bounds__(256) void cvt_all_kernel(CvtArgs a)
{
    long i = (long)blockIdx.x * 256 + threadIdx.x;
    int  seg;
    long loc;
    if      (i < CVT_CUM1) { seg = 0; loc = i; }
    else if (i < CVT_CUM2) { seg = 1; loc = i - CVT_CUM1; }
    else if (i < CVT_CUM3) { seg = 2; loc = i - CVT_CUM2; }
    else if (i < CVT_CUM4) { seg = 3; loc = i - CVT_CUM3; }
    else if (i < CVT_CUM5) { seg = 4; loc = i - CVT_CUM4; }
    else if (i < CVT_CUM6) { seg = 5; loc = i - CVT_CUM5; }
    else                   { seg = 6; loc = i - CVT_CUM6; }

    float4 v = a.src[seg][loc];
    int nin4 = CVT_NIN4[seg];
    long row = loc / nin4;
    int  c4  = (int)(loc - row * nin4) * 4;
    uint4 t = make_uint4(f2tf32(v.x), f2tf32(v.y), f2tf32(v.z), f2tf32(v.w));
    *(uint4*)&a.dst[seg][row * (long)CVT_NOUT[seg] + CVT_COFF[seg] + c4] = t;
}

// ---------------------------------------------------------------------------
// mma.sync tf32 GEMM:  C[M,N] = A[M,K] @ B[K,N]  (row-major, tf32-bit inputs)
// MODE 0: exact fp32 C.  MODE 1 (QKVA): split qc/ckv epilogue.
// MODE 2: tf32 bits of acc*scale.
// v4: cp.async for chunk it+2 is issued right after the barrier (full chunk
// of MMA work as latency slack) instead of at the chunk tail.
// ---------------------------------------------------------------------------
static constexpr int A_LD = 36;
static constexpr int B_LD = 136;
static constexpr int A_FLOATS = 128 * A_LD;
static constexpr int B_FLOATS = 32 * B_LD;
static constexpr int STAGE_FLOATS = A_FLOATS + B_FLOATS;
static constexpr int GEMM_STAGES = 3;
static constexpr int GEMM_SMEM_BYTES = GEMM_STAGES * STAGE_FLOATS * 4;  // 107,520

template <int MODE>
__global__ __launch_bounds__(256, 2) void gemm_mma(
    const float* __restrict__ A, const float* __restrict__ B,
    float* __restrict__ C, float* __restrict__ Cckv, float* __restrict__ Cckvt,
    int M, int N, int K, float scale)
{
    extern __shared__ uint32_t smu[];
    const uint32_t sbase = smem_u32(smu);

    const int tid  = threadIdx.x;
    const int wid  = tid >> 5;
    const int lane = tid & 31;
    const int warpM = wid >> 2;
    const int warpN = wid & 3;
    const int m0 = blockIdx.y * 128;
    const int n0 = blockIdx.x * 128;
    const int r  = lane >> 2;
    const int cq = lane & 3;

    const int arow = tid >> 3;
    const int ac4  = (tid & 7) << 2;
    const int brow = tid >> 5;
    const int bn4  = (tid & 31) << 2;

    float acc[4][4][4];
#pragma unroll
    for (int mi = 0; mi < 4; mi++)
#pragma unroll
        for (int nj = 0; nj < 4; nj++)
#pragma unroll
            for (int t = 0; t < 4; t++) acc[mi][nj][t] = 0.f;

    const int KT = K >> 5;

    auto issue = [&](int it) {
        const int s = it % GEMM_STAGES;
        const uint32_t as = sbase + (uint32_t)(s * STAGE_FLOATS) * 4u;
        const uint32_t bs = as + (uint32_t)A_FLOATS * 4u;
        const int k0 = it << 5;
#pragma unroll
        for (int i = 0; i < 4; i++) {
            int row = arow + i * 32;
            cp_async16(as + (uint32_t)(row * A_LD + ac4) * 4u,
                       A + (size_t)(m0 + row) * K + k0 + ac4);
        }
#pragma unroll
        for (int i = 0; i < 4; i++) {
            int row = brow + i * 8;
            cp_async16(bs + (uint32_t)(row * B_LD + bn4) * 4u,
                       B + (size_t)(k0 + row) * N + n0 + bn4);
        }
    };

    issue(0); CP_COMMIT();
    issue(1); CP_COMMIT();

    for (int it = 0; it < KT; ++it) {
        CP_WAIT1();
        __syncthreads();
        // stage (it+2)%3 == (it-1)%3 was fully consumed before this barrier
        if (it + 2 < KT) issue(it + 2);
        CP_COMMIT();

        const uint32_t* as = smu + (it % GEMM_STAGES) * STAGE_FLOATS;
        const uint32_t* bs = as + A_FLOATS;
#pragma unroll
        for (int ks = 0; ks < 4; ++ks) {
            uint32_t af[4][4];
#pragma unroll
            for (int mi = 0; mi < 4; mi++) {
                int rb = (warpM * 64 + mi * 16 + r) * A_LD + ks * 8 + cq;
                af[mi][0] = as[rb];
                af[mi][1] = as[rb + 8 * A_LD];
                af[mi][2] = as[rb + 4];
                af[mi][3] = as[rb + 8 * A_LD + 4];
            }
            uint32_t bf[4][2];
#pragma unroll
            for (int nj = 0; nj < 4; nj++) {
                int bb = (ks * 8 + cq) * B_LD + warpN * 32 + nj * 8 + r;
                bf[nj][0] = bs[bb];
                bf[nj][1] = bs[bb + 4 * B_LD];
            }
#pragma unroll
            for (int mi = 0; mi < 4; mi++)
#pragma unroll
                for (int nj = 0; nj < 4; nj++)
                    mma_tf32(acc[mi][nj], af[mi], bf[nj]);
        }
    }

#pragma unroll
    for (int mi = 0; mi < 4; mi++) {
        const int row0 = m0 + warpM * 64 + mi * 16 + r;
#pragma unroll
        for (int nj = 0; nj < 4; nj++) {
            const int col = n0 + warpN * 32 + nj * 8 + 2 * cq;
            if (MODE == 1) {
                if (col < QRANK) {
                    *(uint2*)&C[(size_t)row0 * QRANK + col] =
                        make_uint2(f2tf32(acc[mi][nj][0]), f2tf32(acc[mi][nj][1]));
                    *(uint2*)&C[(size_t)(row0 + 8) * QRANK + col] =
                        make_uint2(f2tf32(acc[mi][nj][2]), f2tf32(acc[mi][nj][3]));
                } else {
                    int colr = col - QRANK;
                    size_t o0 = (size_t)row0 * KVRANK + colr;
                    size_t o1 = (size_t)(row0 + 8) * KVRANK + colr;
                    *(float2*)&Cckv[o0] = make_float2(acc[mi][nj][0], acc[mi][nj][1]);
                    *(float2*)&Cckv[o1] = make_float2(acc[mi][nj][2], acc[mi][nj][3]);
                    *(uint2*)&Cckvt[o0] =
                        make_uint2(f2tf32(acc[mi][nj][0]), f2tf32(acc[mi][nj][1]));
                    *(uint2*)&Cckvt[o1] =
                        make_uint2(f2tf32(acc[mi][nj][2]), f2tf32(acc[mi][nj][3]));
                }
            } else if (MODE == 2) {
                *(uint2*)&C[(size_t)row0 * N + col] =
                    make_uint2(f2tf32(acc[mi][nj][0] * scale),
                               f2tf32(acc[mi][nj][1] * scale));
                *(uint2*)&C[(size_t)(row0 + 8) * N + col] =
                    make_uint2(f2tf32(acc[mi][nj][2] * scale),
                               f2tf32(acc[mi][nj][3] * scale));
            } else {
                *(float2*)&C[(size_t)row0 * N + col] =
                    make_float2(acc[mi][nj][0], acc[mi][nj][1]);
                *(float2*)&C[(size_t)(row0 + 8) * N + col] =
                    make_float2(acc[mi][nj][2], acc[mi][nj][3]);
            }
        }
    }
}

// ---------------------------------------------------------------------------
// Tensor-core flash attention (causal), tf32 mma + fp32 online softmax.
// Q (pre-scaled tf32 bits) and KV (tf32 bits) are loaded with plain LDG+STS
// raw uint4 copies (the verified round-10 pattern, minus the cvt work —
// values are pre-rounded upstream). KV layout [tokens, 8192]: K at head*128,
// V at 4096 + head*128.
// ---------------------------------------------------------------------------
static constexpr int FQ = 128;
static constexpr int FK = 64;
static constexpr int K_LD = 132;
static constexpr int V_LD = 136;
static constexpr int P_LD = 68;
static constexpr int KW  = 64 * K_LD;
static constexpr int VW  = 64 * V_LD;
static constexpr int PW  = 128 * P_LD;
static constexpr int QFW = 128 * 128;
static constexpr int FLASH_SMEM_BYTES = (KW + VW + PW + QFW) * 4;

__global__ __launch_bounds__(256) void flash_tc(
    const float* __restrict__ Q, const float* __restrict__ KV,
    float* __restrict__ O)
{
    extern __shared__ uint32_t fsm[];
    uint32_t* Ks = fsm;
    uint32_t* Vs = fsm + KW;
    uint32_t* Ps = fsm + KW + VW;
    uint32_t* Qf = fsm + KW + VW + PW;

    const int tid  = threadIdx.x;
    const int wq   = tid >> 5;
    const int lane = tid & 31;
    const int r    = lane >> 2;
    const int cq   = lane & 3;
    const int mtile = blockIdx.x;
    const int head  = blockIdx.y;
    const int b     = blockIdx.z;
    const int m0    = mtile * FQ;
    const size_t baseQ  = ((size_t)b * SEQ) * MODEL + (size_t)head * HDIM;
    const size_t baseKV = ((size_t)b * SEQ) * NKV   + (size_t)head * HDIM;

    // ---- stage Q: raw uint4 copies (128 rows x 32 float4 slots) ----
    for (int it = tid; it < 128 * 32; it += 256) {
        int row = it >> 5, c4 = (it & 31) << 2;
        uint4 t = *(const uint4*)&Q[baseQ + (size_t)(m0 + row) * MODEL + c4];
        *(uint4*)&fsm[row * K_LD + c4] = t;
    }
    __syncthreads();

    // ---- repack Q into fragment-ordered smem ----
#pragma unroll
    for (int ks = 0; ks < 16; ks++) {
        int rb = (wq * 16 + r) * K_LD + ks * 8 + cq;
        uint4 qv = { fsm[rb], fsm[rb + 8 * K_LD],
                     fsm[rb + 4], fsm[rb + 8 * K_LD + 4] };
        *(uint4*)&Qf[(((wq * 16 + ks) * 32) + lane) * 4] = qv;
    }
    __syncthreads();

    float of[16][4];
#pragma unroll
    for (int nj = 0; nj < 16; nj++)
#pragma unroll
        for (int t = 0; t < 4; t++) of[nj][t] = 0.f;

    float mrow0 = -1e30f, mrow1 = -1e30f, lrow0 = 0.f, lrow1 = 0.f;
    const int row0 = m0 + wq * 16 + r;
    const int row1 = row0 + 8;

    const int NT = 2 * (mtile + 1);
    for (int t = 0; t < NT; t++) {
        const int n0 = t * FK;

        // ---- load KV tile: raw uint4 copies (64 rows x 32 slots each) ----
        for (int it = tid; it < 64 * 32; it += 256) {
            int row = it >> 5, c4 = (it & 31) << 2;
            size_t g = baseKV + (size_t)(n0 + row) * NKV + c4;
            uint4 tk = *(const uint4*)&KV[g];
            uint4 tv = *(const uint4*)&KV[g + MODEL];
            *(uint4*)&Ks[row * K_LD + c4] = tk;
            *(uint4*)&Vs[row * V_LD + c4] = tv;
        }
        __syncthreads();

        float sc[8][4];
#pragma unroll
        for (int nj = 0; nj < 8; nj++)
#pragma unroll
            for (int e = 0; e < 4; e++) sc[nj][e] = 0.f;

#pragma unroll
        for (int ks = 0; ks < 16; ks++) {
            uint4 qa4 = *(const uint4*)&Qf[(((wq * 16 + ks) * 32) + lane) * 4];
            uint32_t qa[4] = { qa4.x, qa4.y, qa4.z, qa4.w };
            uint32_t bf[8][2];
#pragma unroll
            for (int nj = 0; nj < 8; nj++) {
                int ib = (nj * 8 + r) * K_LD + ks * 8 + cq;
                bf[nj][0] = Ks[ib];
                bf[nj][1] = Ks[ib + 4];
            }
#pragma unroll
            for (int nj = 0; nj < 8; nj++)
                mma_tf32(sc[nj], qa, bf[nj]);
        }

        if (n0 + FK - 1 > m0) {
#pragma unroll
            for (int nj = 0; nj < 8; nj++) {
                int kk = n0 + nj * 8 + 2 * cq;
                if (kk     > row0) sc[nj][0] = -1e30f;
                if (kk + 1 > row0) sc[nj][1] = -1e30f;
                if (kk     > row1) sc[nj][2] = -1e30f;
                if (kk + 1 > row1) sc[nj][3] = -1e30f;
            }
        }

        float tmax0 = -1e30f, tmax1 = -1e30f;
#pragma unroll
        for (int nj = 0; nj < 8; nj++) {
            tmax0 = fmaxf(tmax0, fmaxf(sc[nj][0], sc[nj][1]));
            tmax1 = fmaxf(tmax1, fmaxf(sc[nj][2], sc[nj][3]));
        }
        tmax0 = fmaxf(tmax0, __shfl_xor_sync(0xffffffffu, tmax0, 1));
        tmax0 = fmaxf(tmax0, __shfl_xor_sync(0xffffffffu, tmax0, 2));
        tmax1 = fmaxf(tmax1, __shfl_xor_sync(0xffffffffu, tmax1, 1));
        tmax1 = fmaxf(tmax1, __shfl_xor_sync(0xffffffffu, tmax1, 2));

        float nm0 = fmaxf(mrow0, tmax0);
        float nm1 = fmaxf(mrow1, tmax1);
        float c0 = __expf(mrow0 - nm0);
        float c1 = __expf(mrow1 - nm1);
        float ts0 = 0.f, ts1 = 0.f;
#pragma unroll
        for (int nj = 0; nj < 8; nj++) {
            float p0 = __expf(sc[nj][0] - nm0);
            float p1 = __expf(sc[nj][1] - nm0);
            float p2 = __expf(sc[nj][2] - nm1);
            float p3 = __expf(sc[nj][3] - nm1);
            ts0 += p0 + p1;
            ts1 += p2 + p3;
            uint2 u0 = { f2tf32(p0), f2tf32(p1) };
            uint2 u1 = { f2tf32(p2), f2tf32(p3) };
            *(uint2*)&Ps[(wq * 16 + r) * P_LD + nj * 8 + 2 * cq]     = u0;
            *(uint2*)&Ps[(wq * 16 + r + 8) * P_LD + nj * 8 + 2 * cq] = u1;
        }
        ts0 += __shfl_xor_sync(0xffffffffu, ts0, 1);
        ts0 += __shfl_xor_sync(0xffffffffu, ts0, 2);
        ts1 += __shfl_xor_sync(0xffffffffu, ts1, 1);
        ts1 += __shfl_xor_sync(0xffffffffu, ts1, 2);

        mrow0 = nm0; mrow1 = nm1;
        lrow0 = lrow0 * c0 + ts0;
        lrow1 = lrow1 * c1 + ts1;
#pragma unroll
        for (int nj = 0; nj < 16; nj++) {
            of[nj][0] *= c0; of[nj][1] *= c0;
            of[nj][2] *= c1; of[nj][3] *= c1;
        }
        __syncwarp();

#pragma unroll
        for (int ks = 0; ks < 8; ks++) {
            uint32_t ap[4];
            int rb = (wq * 16 + r) * P_LD + ks * 8 + cq;
            ap[0] = Ps[rb];
            ap[1] = Ps[rb + 8 * P_LD];
            ap[2] = Ps[rb + 4];
            ap[3] = Ps[rb + 8 * P_LD + 4];
            uint32_t bf[16][2];
#pragma unroll
            for (int nj = 0; nj < 16; nj++) {
                int ib = (ks * 8 + cq) * V_LD + nj * 8 + r;
                bf[nj][0] = Vs[ib];
                bf[nj][1] = Vs[ib + 4 * V_LD];
            }
#pragma unroll
            for (int nj = 0; nj < 16; nj++)
                mma_tf32(of[nj], ap, bf[nj]);
        }
        __syncthreads();
    }

    const float inv0 = 1.f / lrow0;
    const float inv1 = 1.f / lrow1;
#pragma unroll
    for (int nj = 0; nj < 16; nj++) {
        int col = nj * 8 + 2 * cq;
        *(uint2*)&O[baseQ + (size_t)row0 * MODEL + col] =
            make_uint2(f2tf32(of[nj][0] * inv0), f2tf32(of[nj][1] * inv0));
        *(uint2*)&O[baseQ + (size_t)row1 * MODEL + col] =
            make_uint2(f2tf32(of[nj][2] * inv1), f2tf32(of[nj][3] * inv1));
    }
}

// ---------------------------------------------------------------------------
// Launch
// ---------------------------------------------------------------------------
extern "C" void kernel_launch(void* const* d_in, const int* in_sizes, int n_in,
                              void* d_out, int out_size)
{
    (void)in_sizes; (void)n_in; (void)out_size;
    const float* X     = (const float*)d_in[0];
    const float* w_qa  = (const float*)d_in[1];
    const float* w_qb  = (const float*)d_in[2];
    const float* w_kva = (const float*)d_in[3];
    const float* w_kb  = (const float*)d_in[4];
    const float* w_vb  = (const float*)d_in[5];
    const float* w_o   = (const float*)d_in[6];

    float* attn_out = (float*)d_out;
    float* ckv      = (float*)d_out + (size_t)TOKENS * HID;

    float *qc, *q, *kv, *ao, *xt, *ckvt, *wqkva, *wqb, *wkv8, *wo;
    cudaGetSymbolAddress((void**)&qc,    g_qc);
    cudaGetSymbolAddress((void**)&q,     g_q);
    cudaGetSymbolAddress((void**)&kv,    g_kv);
    cudaGetSymbolAddress((void**)&ao,    g_ao);
    cudaGetSymbolAddress((void**)&xt,    g_xt);
    cudaGetSymbolAddress((void**)&ckvt,  g_ckvt);
    cudaGetSymbolAddress((void**)&wqkva, g_wqkva);
    cudaGetSymbolAddress((void**)&wqb,   g_wqb);
    cudaGetSymbolAddress((void**)&wkv8,  g_wkv8);
    cudaGetSymbolAddress((void**)&wo,    g_wo);

    cudaFuncSetAttribute(gemm_mma<0>,
                         cudaFuncAttributeMaxDynamicSharedMemorySize, GEMM_SMEM_BYTES);
    cudaFuncSetAttribute(gemm_mma<1>,
                         cudaFuncAttributeMaxDynamicSharedMemorySize, GEMM_SMEM_BYTES);
    cudaFuncSetAttribute(gemm_mma<2>,
                         cudaFuncAttributeMaxDynamicSharedMemorySize, GEMM_SMEM_BYTES);
    cudaFuncSetAttribute(flash_tc,
                         cudaFuncAttributeMaxDynamicSharedMemorySize, FLASH_SMEM_BYTES);

    cudaStream_t stream = 0;

    // ---- launch 1: fused tf32 conversion pre-pass ----
    CvtArgs ca;
    ca.src[0] = (const float4*)X;     ca.dst[0] = xt;
    ca.src[1] = (const float4*)w_qa;  ca.dst[1] = wqkva;
    ca.src[2] = (const float4*)w_kva; ca.dst[2] = wqkva;
    ca.src[3] = (const float4*)w_qb;  ca.dst[3] = wqb;
    ca.src[4] = (const float4*)w_kb;  ca.dst[4] = wkv8;
    ca.src[5] = (const float4*)w_vb;  ca.dst[5] = wkv8;
    ca.src[6] = (const float4*)w_o;   ca.dst[6] = wo;
    cvt_all_kernel<<<CVT_BLOCKS, 256, 0, stream>>>(ca);

    // ---- launch 2: fused qc+ckv projection ----
    {
        dim3 grid(NQKVA / 128, TOKENS / 128);
        gemm_mma<1><<<grid, 256, GEMM_SMEM_BYTES, stream>>>(
            xt, wqkva, qc, ckv, ckvt, TOKENS, NQKVA, HID, 1.f);
    }
    // ---- launch 3: q projection (stores pre-scaled tf32 bits) ----
    {
        dim3 grid(MODEL / 128, TOKENS / 128);
        gemm_mma<2><<<grid, 256, GEMM_SMEM_BYTES, stream>>>(
            qc, wqb, q, nullptr, nullptr, TOKENS, MODEL, QRANK, SM_SCALE);
    }
    // ---- launch 4: fused k+v projection (stores tf32 bits) ----
    {
        dim3 grid(NKV / 128, TOKENS / 128);
        gemm_mma<2><<<grid, 256, GEMM_SMEM_BYTES, stream>>>(
            ckvt, wkv8, kv, nullptr, nullptr, TOKENS, NKV, KVRANK, 1.f);
    }
    // ---- launch 5: causal attention ----
    dim3 fgrid(SEQ / FQ, NHEADS, BATCH);
    flash_tc<<<fgrid, 256, FLASH_SMEM_BYTES, stream>>>(q, kv, ao);

    // ---- launch 6 (profiled by -s 5): output projection ----
    {
        dim3 grid(HID / 128, TOKENS / 128);
        gemm_mma<0><<<grid, 256, GEMM_SMEM_BYTES, stream>>>(
            ao, wo, attn_out, nullptr, nullptr, TOKENS, HID, MODEL, 1.f);
    }
}

// round 14
// speedup vs baseline: 1.0559x; 1.0559x over previous
#include <cuda_runtime.h>
#include <cuda_bf16.h>
#include <cstdint>
#include <cstddef>

// ---------------------------------------------------------------------------
// Problem constants
// ---------------------------------------------------------------------------
static constexpr int BATCH   = 2;
static constexpr int SEQ     = 2048;
static constexpr int HID     = 4096;
static constexpr int NHEADS  = 32;
static constexpr int HDIM    = 128;
static constexpr int QRANK   = 1536;
static constexpr int KVRANK  = 512;
static constexpr int TOKENS  = BATCH * SEQ;            // 4096
static constexpr int MODEL   = NHEADS * HDIM;          // 4096
static constexpr int NQKVA   = QRANK + KVRANK;         // 2048
static constexpr int NKV     = 2 * MODEL;              // 8192
static constexpr float SM_SCALE = 0.08838834764831845f; // 1/sqrt(128)

// ---------------------------------------------------------------------------
// Scratch (static device allocations; no cudaMalloc anywhere)
// ---------------------------------------------------------------------------
__device__ float g_qc  [(size_t)TOKENS * QRANK];       // tf32 bits
__device__ float g_q   [(size_t)TOKENS * MODEL];       // tf32 bits, pre-scaled
__device__ float g_kv  [(size_t)TOKENS * NKV];         // tf32 bits: K cols 0-4095, V cols 4096-8191
__device__ float g_ao  [(size_t)TOKENS * MODEL];       // tf32 bits
__device__ float g_xt  [(size_t)TOKENS * HID];         // tf32 bits
__device__ float g_ckvt[(size_t)TOKENS * KVRANK];      // tf32 bits
__device__ float g_wqkva[(size_t)HID   * NQKVA];       // [wqa | wkva], tf32 bits
__device__ float g_wqb [(size_t)QRANK  * MODEL];       // tf32 bits
__device__ float g_wkv8[(size_t)KVRANK * NKV];         // [wkb | wvb], tf32 bits
__device__ float g_wo  [(size_t)MODEL  * HID];         // tf32 bits

// ---------------------------------------------------------------------------
// Helpers
// ---------------------------------------------------------------------------
__device__ __forceinline__ uint32_t f2tf32(float x) {
    uint32_t r;
    asm("cvt.rna.tf32.f32 %0, %1;" : "=r"(r) : "f"(x));
    return r;
}
__device__ __forceinline__ uint32_t smem_u32(const void* p) {
    uint32_t a;
    asm("{ .reg .u64 t; cvta.to.shared.u64 t, %1; cvt.u32.u64 %0, t; }"
        : "=r"(a) : "l"(p));
    return a;
}
__device__ __forceinline__ void cp_async16(uint32_t s, const void* g) {
    asm volatile("cp.async.cg.shared.global [%0], [%1], 16;" :: "r"(s), "l"(g));
}
#define CP_COMMIT() asm volatile("cp.async.commit_group;" ::: "memory")
#define CP_WAIT1()  asm volatile("cp.async.wait_group 1;" ::: "memory")

__device__ __forceinline__ void mma_tf32(float c[4], const uint32_t a[4],
                                         const uint32_t b[2]) {
    asm volatile(
        "mma.sync.aligned.m16n8k8.row.col.f32.tf32.tf32.f32 "
        "{%0,%1,%2,%3}, {%4,%5,%6,%7}, {%8,%9}, {%0,%1,%2,%3};"
        : "+f"(c[0]), "+f"(c[1]), "+f"(c[2]), "+f"(c[3])
        : "r"(a[0]), "r"(a[1]), "r"(a[2]), "r"(a[3]), "r"(b[0]), "r"(b[1]));
}

// ---------------------------------------------------------------------------
// Fused tf32 conversion pre-pass: one launch handles all 7 segments.
// ---------------------------------------------------------------------------
struct CvtArgs {
    const float4* src[7];
    float*        dst[7];
};

__constant__ const int CVT_NIN4[7] = {1024, 384, 128, 1024, 1024, 1024, 1024};
__constant__ const int CVT_NOUT[7] = {HID, NQKVA, NQKVA, MODEL, NKV, NKV, HID};
__constant__ const int CVT_COFF[7] = {0, 0, QRANK, 0, 0, MODEL, 0};
static constexpr long CVT_N4[7] = {
    (long)TOKENS * HID / 4,     // X
    (long)HID * QRANK / 4,      // w_qa
    (long)HID * KVRANK / 4,     // w_kva
    (long)QRANK * MODEL / 4,    // w_qb
    (long)KVRANK * MODEL / 4,   // w_kb
    (long)KVRANK * MODEL / 4,   // w_vb
    (long)MODEL * HID / 4       // w_o
};
static constexpr long CVT_CUM0 = 0;
static constexpr long CVT_CUM1 = CVT_CUM0 + CVT_N4[0];
static constexpr long CVT_CUM2 = CVT_CUM1 + CVT_N4[1];
static constexpr long CVT_CUM3 = CVT_CUM2 + CVT_N4[2];
static constexpr long CVT_CUM4 = CVT_CUM3 + CVT_N4[3];
static constexpr long CVT_CUM5 = CVT_CUM4 + CVT_N4[4];
static constexpr long CVT_CUM6 = CVT_CUM5 + CVT_N4[5];
static constexpr long CVT_TOTAL = CVT_CUM6 + CVT_N4[6];
static constexpr int  CVT_BLOCKS = (int)(CVT_TOTAL / 256);

__global__ __launch_bounds__(256) void cvt_all_kernel(CvtArgs a)
{
    long i = (long)blockIdx.x * 256 + threadIdx.x;
    int  seg;
    long loc;
    if      (i < CVT_CUM1) { seg = 0; loc = i; }
    else if (i < CVT_CUM2) { seg = 1; loc = i - CVT_CUM1; }
    else if (i < CVT_CUM3) { seg = 2; loc = i - CVT_CUM2; }
    else if (i < CVT_CUM4) { seg = 3; loc = i - CVT_CUM3; }
    else if (i < CVT_CUM5) { seg = 4; loc = i - CVT_CUM4; }
    else if (i < CVT_CUM6) { seg = 5; loc = i - CVT_CUM5; }
    else                   { seg = 6; loc = i - CVT_CUM6; }

    float4 v = a.src[seg][loc];
    int nin4 = CVT_NIN4[seg];
    long row = loc / nin4;
    int  c4  = (int)(loc - row * nin4) * 4;
    uint4 t = make_uint4(f2tf32(v.x), f2tf32(v.y), f2tf32(v.z), f2tf32(v.w));
    *(uint4*)&a.dst[seg][row * (long)CVT_NOUT[seg] + CVT_COFF[seg] + c4] = t;
}

// ---------------------------------------------------------------------------
// mma.sync tf32 GEMM:  C[M,N] = A[M,K] @ B[K,N]  (row-major, tf32-bit inputs)
// MODE 0: exact fp32 C.  MODE 1 (QKVA): split qc/ckv epilogue.
// MODE 2: tf32 bits of acc*scale.
// Tail-issue cp.async schedule (fastest measured variant, round 12).
// ---------------------------------------------------------------------------
static constexpr int A_LD = 36;
static constexpr int B_LD = 136;
static constexpr int A_FLOATS = 128 * A_LD;
static constexpr int B_FLOATS = 32 * B_LD;
static constexpr int STAGE_FLOATS = A_FLOATS + B_FLOATS;
static constexpr int GEMM_STAGES = 3;
static constexpr int GEMM_SMEM_BYTES = GEMM_STAGES * STAGE_FLOATS * 4;  // 107,520

template <int MODE>
__global__ __launch_bounds__(256, 2) void gemm_mma(
    const float* __restrict__ A, const float* __restrict__ B,
    float* __restrict__ C, float* __restrict__ Cckv, float* __restrict__ Cckvt,
    int M, int N, int K, float scale)
{
    extern __shared__ uint32_t smu[];
    const uint32_t sbase = smem_u32(smu);

    const int tid  = threadIdx.x;
    const int wid  = tid >> 5;
    const int lane = tid & 31;
    const int warpM = wid >> 2;
    const int warpN = wid & 3;
    const int m0 = blockIdx.y * 128;
    const int n0 = blockIdx.x * 128;
    const int r  = lane >> 2;
    const int cq = lane & 3;

    const int arow = tid >> 3;
    const int ac4  = (tid & 7) << 2;
    const int brow = tid >> 5;
    const int bn4  = (tid & 31) << 2;

    float acc[4][4][4];
#pragma unroll
    for (int mi = 0; mi < 4; mi++)
#pragma unroll
        for (int nj = 0; nj < 4; nj++)
#pragma unroll
            for (int t = 0; t < 4; t++) acc[mi][nj][t] = 0.f;

    const int KT = K >> 5;

    auto issue = [&](int it) {
        const int s = it % GEMM_STAGES;
        const uint32_t as = sbase + (uint32_t)(s * STAGE_FLOATS) * 4u;
        const uint32_t bs = as + (uint32_t)A_FLOATS * 4u;
        const int k0 = it << 5;
#pragma unroll
        for (int i = 0; i < 4; i++) {
            int row = arow + i * 32;
            cp_async16(as + (uint32_t)(row * A_LD + ac4) * 4u,
                       A + (size_t)(m0 + row) * K + k0 + ac4);
        }
#pragma unroll
        for (int i = 0; i < 4; i++) {
            int row = brow + i * 8;
            cp_async16(bs + (uint32_t)(row * B_LD + bn4) * 4u,
                       B + (size_t)(k0 + row) * N + n0 + bn4);
        }
    };

    issue(0); CP_COMMIT();
    issue(1); CP_COMMIT();

    for (int it = 0; it < KT; ++it) {
        CP_WAIT1();
        __syncthreads();

        const uint32_t* as = smu + (it % GEMM_STAGES) * STAGE_FLOATS;
        const uint32_t* bs = as + A_FLOATS;
#pragma unroll
        for (int ks = 0; ks < 4; ++ks) {
            uint32_t af[4][4];
#pragma unroll
            for (int mi = 0; mi < 4; mi++) {
                int rb = (warpM * 64 + mi * 16 + r) * A_LD + ks * 8 + cq;
                af[mi][0] = as[rb];
                af[mi][1] = as[rb + 8 * A_LD];
                af[mi][2] = as[rb + 4];
                af[mi][3] = as[rb + 8 * A_LD + 4];
            }
            uint32_t bf[4][2];
#pragma unroll
            for (int nj = 0; nj < 4; nj++) {
                int bb = (ks * 8 + cq) * B_LD + warpN * 32 + nj * 8 + r;
                bf[nj][0] = bs[bb];
                bf[nj][1] = bs[bb + 4 * B_LD];
            }
#pragma unroll
            for (int mi = 0; mi < 4; mi++)
#pragma unroll
                for (int nj = 0; nj < 4; nj++)
                    mma_tf32(acc[mi][nj], af[mi], bf[nj]);
        }

        if (it + 2 < KT) issue(it + 2);
        CP_COMMIT();
    }

#pragma unroll
    for (int mi = 0; mi < 4; mi++) {
        const int row0 = m0 + warpM * 64 + mi * 16 + r;
#pragma unroll
        for (int nj = 0; nj < 4; nj++) {
            const int col = n0 + warpN * 32 + nj * 8 + 2 * cq;
            if (MODE == 1) {
                if (col < QRANK) {
                    *(uint2*)&C[(size_t)row0 * QRANK + col] =
                        make_uint2(f2tf32(acc[mi][nj][0]), f2tf32(acc[mi][nj][1]));
                    *(uint2*)&C[(size_t)(row0 + 8) * QRANK + col] =
                        make_uint2(f2tf32(acc[mi][nj][2]), f2tf32(acc[mi][nj][3]));
                } else {
                    int colr = col - QRANK;
                    size_t o0 = (size_t)row0 * KVRANK + colr;
                    size_t o1 = (size_t)(row0 + 8) * KVRANK + colr;
                    *(float2*)&Cckv[o0] = make_float2(acc[mi][nj][0], acc[mi][nj][1]);
                    *(float2*)&Cckv[o1] = make_float2(acc[mi][nj][2], acc[mi][nj][3]);
                    *(uint2*)&Cckvt[o0] =
                        make_uint2(f2tf32(acc[mi][nj][0]), f2tf32(acc[mi][nj][1]));
                    *(uint2*)&Cckvt[o1] =
                        make_uint2(f2tf32(acc[mi][nj][2]), f2tf32(acc[mi][nj][3]));
                }
            } else if (MODE == 2) {
                *(uint2*)&C[(size_t)row0 * N + col] =
                    make_uint2(f2tf32(acc[mi][nj][0] * scale),
                               f2tf32(acc[mi][nj][1] * scale));
                *(uint2*)&C[(size_t)(row0 + 8) * N + col] =
                    make_uint2(f2tf32(acc[mi][nj][2] * scale),
                               f2tf32(acc[mi][nj][3] * scale));
            } else {
                *(float2*)&C[(size_t)row0 * N + col] =
                    make_float2(acc[mi][nj][0], acc[mi][nj][1]);
                *(float2*)&C[(size_t)(row0 + 8) * N + col] =
                    make_float2(acc[mi][nj][2], acc[mi][nj][3]);
            }
        }
    }
}

// ---------------------------------------------------------------------------
// Tensor-core flash attention (causal), tf32 mma + fp32 online softmax.
// Q (pre-scaled tf32 bits) and KV (tf32 bits) loaded with plain LDG+STS raw
// uint4 copies (verified round-10 pattern minus cvt work). KV layout
// [tokens, 8192]: K at head*128, V at 4096 + head*128.
// ---------------------------------------------------------------------------
static constexpr int FQ = 128;
static constexpr int FK = 64;
static constexpr int K_LD = 132;
static constexpr int V_LD = 136;
static constexpr int P_LD = 68;
static constexpr int KW  = 64 * K_LD;
static constexpr int VW  = 64 * V_LD;
static constexpr int PW  = 128 * P_LD;
static constexpr int QFW = 128 * 128;
static constexpr int FLASH_SMEM_BYTES = (KW + VW + PW + QFW) * 4;

__global__ __launch_bounds__(256) void flash_tc(
    const float* __restrict__ Q, const float* __restrict__ KV,
    float* __restrict__ O)
{
    extern __shared__ uint32_t fsm[];
    uint32_t* Ks = fsm;
    uint32_t* Vs = fsm + KW;
    uint32_t* Ps = fsm + KW + VW;
    uint32_t* Qf = fsm + KW + VW + PW;

    const int tid  = threadIdx.x;
    const int wq   = tid >> 5;
    const int lane = tid & 31;
    const int r    = lane >> 2;
    const int cq   = lane & 3;
    const int mtile = blockIdx.x;
    const int head  = blockIdx.y;
    const int b     = blockIdx.z;
    const int m0    = mtile * FQ;
    const size_t baseQ  = ((size_t)b * SEQ) * MODEL + (size_t)head * HDIM;
    const size_t baseKV = ((size_t)b * SEQ) * NKV   + (size_t)head * HDIM;

    // ---- stage Q: raw uint4 copies (128 rows x 32 float4 slots) ----
    for (int it = tid; it < 128 * 32; it += 256) {
        int row = it >> 5, c4 = (it & 31) << 2;
        uint4 t = *(const uint4*)&Q[baseQ + (size_t)(m0 + row) * MODEL + c4];
        *(uint4*)&fsm[row * K_LD + c4] = t;
    }
    __syncthreads();

    // ---- repack Q into fragment-ordered smem ----
#pragma unroll
    for (int ks = 0; ks < 16; ks++) {
        int rb = (wq * 16 + r) * K_LD + ks * 8 + cq;
        uint4 qv = { fsm[rb], fsm[rb + 8 * K_LD],
                     fsm[rb + 4], fsm[rb + 8 * K_LD + 4] };
        *(uint4*)&Qf[(((wq * 16 + ks) * 32) + lane) * 4] = qv;
    }
    __syncthreads();

    float of[16][4];
#pragma unroll
    for (int nj = 0; nj < 16; nj++)
#pragma unroll
        for (int t = 0; t < 4; t++) of[nj][t] = 0.f;

    float mrow0 = -1e30f, mrow1 = -1e30f, lrow0 = 0.f, lrow1 = 0.f;
    const int row0 = m0 + wq * 16 + r;
    const int row1 = row0 + 8;

    const int NT = 2 * (mtile + 1);
    for (int t = 0; t < NT; t++) {
        const int n0 = t * FK;

        // ---- load KV tile: raw uint4 copies (64 rows x 32 slots each) ----
        for (int it = tid; it < 64 * 32; it += 256) {
            int row = it >> 5, c4 = (it & 31) << 2;
            size_t g = baseKV + (size_t)(n0 + row) * NKV + c4;
            uint4 tk = *(const uint4*)&KV[g];
            uint4 tv = *(const uint4*)&KV[g + MODEL];
            *(uint4*)&Ks[row * K_LD + c4] = tk;
            *(uint4*)&Vs[row * V_LD + c4] = tv;
        }
        __syncthreads();

        float sc[8][4];
#pragma unroll
        for (int nj = 0; nj < 8; nj++)
#pragma unroll
            for (int e = 0; e < 4; e++) sc[nj][e] = 0.f;

#pragma unroll
        for (int ks = 0; ks < 16; ks++) {
            uint4 qa4 = *(const uint4*)&Qf[(((wq * 16 + ks) * 32) + lane) * 4];
            uint32_t qa[4] = { qa4.x, qa4.y, qa4.z, qa4.w };
            uint32_t bf[8][2];
#pragma unroll
            for (int nj = 0; nj < 8; nj++) {
                int ib = (nj * 8 + r) * K_LD + ks * 8 + cq;
                bf[nj][0] = Ks[ib];
                bf[nj][1] = Ks[ib + 4];
            }
#pragma unroll
            for (int nj = 0; nj < 8; nj++)
                mma_tf32(sc[nj], qa, bf[nj]);
        }

        if (n0 + FK - 1 > m0) {
#pragma unroll
            for (int nj = 0; nj < 8; nj++) {
                int kk = n0 + nj * 8 + 2 * cq;
                if (kk     > row0) sc[nj][0] = -1e30f;
                if (kk + 1 > row0) sc[nj][1] = -1e30f;
                if (kk     > row1) sc[nj][2] = -1e30f;
                if (kk + 1 > row1) sc[nj][3] = -1e30f;
            }
        }

        float tmax0 = -1e30f, tmax1 = -1e30f;
#pragma unroll
        for (int nj = 0; nj < 8; nj++) {
            tmax0 = fmaxf(tmax0, fmaxf(sc[nj][0], sc[nj][1]));
            tmax1 = fmaxf(tmax1, fmaxf(sc[nj][2], sc[nj][3]));
        }
        tmax0 = fmaxf(tmax0, __shfl_xor_sync(0xffffffffu, tmax0, 1));
        tmax0 = fmaxf(tmax0, __shfl_xor_sync(0xffffffffu, tmax0, 2));
        tmax1 = fmaxf(tmax1, __shfl_xor_sync(0xffffffffu, tmax1, 1));
        tmax1 = fmaxf(tmax1, __shfl_xor_sync(0xffffffffu, tmax1, 2));

        float nm0 = fmaxf(mrow0, tmax0);
        float nm1 = fmaxf(mrow1, tmax1);
        float c0 = __expf(mrow0 - nm0);
        float c1 = __expf(mrow1 - nm1);
        float ts0 = 0.f, ts1 = 0.f;
#pragma unroll
        for (int nj = 0; nj < 8; nj++) {
            float p0 = __expf(sc[nj][0] - nm0);
            float p1 = __expf(sc[nj][1] - nm0);
            float p2 = __expf(sc[nj][2] - nm1);
            float p3 = __expf(sc[nj][3] - nm1);
            ts0 += p0 + p1;
            ts1 += p2 + p3;
            uint2 u0 = { f2tf32(p0), f2tf32(p1) };
            uint2 u1 = { f2tf32(p2), f2tf32(p3) };
            *(uint2*)&Ps[(wq * 16 + r) * P_LD + nj * 8 + 2 * cq]     = u0;
            *(uint2*)&Ps[(wq * 16 + r + 8) * P_LD + nj * 8 + 2 * cq] = u1;
        }
        ts0 += __shfl_xor_sync(0xffffffffu, ts0, 1);
        ts0 += __shfl_xor_sync(0xffffffffu, ts0, 2);
        ts1 += __shfl_xor_sync(0xffffffffu, ts1, 1);
        ts1 += __shfl_xor_sync(0xffffffffu, ts1, 2);

        mrow0 = nm0; mrow1 = nm1;
        lrow0 = lrow0 * c0 + ts0;
        lrow1 = lrow1 * c1 + ts1;
#pragma unroll
        for (int nj = 0; nj < 16; nj++) {
            of[nj][0] *= c0; of[nj][1] *= c0;
            of[nj][2] *= c1; of[nj][3] *= c1;
        }
        __syncwarp();

#pragma unroll
        for (int ks = 0; ks < 8; ks++) {
            uint32_t ap[4];
            int rb = (wq * 16 + r) * P_LD + ks * 8 + cq;
            ap[0] = Ps[rb];
            ap[1] = Ps[rb + 8 * P_LD];
            ap[2] = Ps[rb + 4];
            ap[3] = Ps[rb + 8 * P_LD + 4];
            uint32_t bf[16][2];
#pragma unroll
            for (int nj = 0; nj < 16; nj++) {
                int ib = (ks * 8 + cq) * V_LD + nj * 8 + r;
                bf[nj][0] = Vs[ib];
                bf[nj][1] = Vs[ib + 4 * V_LD];
            }
#pragma unroll
            for (int nj = 0; nj < 16; nj++)
                mma_tf32(of[nj], ap, bf[nj]);
        }
        __syncthreads();
    }

    const float inv0 = 1.f / lrow0;
    const float inv1 = 1.f / lrow1;
#pragma unroll
    for (int nj = 0; nj < 16; nj++) {
        int col = nj * 8 + 2 * cq;
        *(uint2*)&O[baseQ + (size_t)row0 * MODEL + col] =
            make_uint2(f2tf32(of[nj][0] * inv0), f2tf32(of[nj][1] * inv0));
        *(uint2*)&O[baseQ + (size_t)row1 * MODEL + col] =
            make_uint2(f2tf32(of[nj][2] * inv1), f2tf32(of[nj][3] * inv1));
    }
}

// ---------------------------------------------------------------------------
// Launch
// ---------------------------------------------------------------------------
extern "C" void kernel_launch(void* const* d_in, const int* in_sizes, int n_in,
                              void* d_out, int out_size)
{
    (void)in_sizes; (void)n_in; (void)out_size;
    const float* X     = (const float*)d_in[0];
    const float* w_qa  = (const float*)d_in[1];
    const float* w_qb  = (const float*)d_in[2];
    const float* w_kva = (const float*)d_in[3];
    const float* w_kb  = (const float*)d_in[4];
    const float* w_vb  = (const float*)d_in[5];
    const float* w_o   = (const float*)d_in[6];

    float* attn_out = (float*)d_out;
    float* ckv      = (float*)d_out + (size_t)TOKENS * HID;

    float *qc, *q, *kv, *ao, *xt, *ckvt, *wqkva, *wqb, *wkv8, *wo;
    cudaGetSymbolAddress((void**)&qc,    g_qc);
    cudaGetSymbolAddress((void**)&q,     g_q);
    cudaGetSymbolAddress((void**)&kv,    g_kv);
    cudaGetSymbolAddress((void**)&ao,    g_ao);
    cudaGetSymbolAddress((void**)&xt,    g_xt);
    cudaGetSymbolAddress((void**)&ckvt,  g_ckvt);
    cudaGetSymbolAddress((void**)&wqkva, g_wqkva);
    cudaGetSymbolAddress((void**)&wqb,   g_wqb);
    cudaGetSymbolAddress((void**)&wkv8,  g_wkv8);
    cudaGetSymbolAddress((void**)&wo,    g_wo);

    cudaFuncSetAttribute(gemm_mma<0>,
                         cudaFuncAttributeMaxDynamicSharedMemorySize, GEMM_SMEM_BYTES);
    cudaFuncSetAttribute(gemm_mma<1>,
                         cudaFuncAttributeMaxDynamicSharedMemorySize, GEMM_SMEM_BYTES);
    cudaFuncSetAttribute(gemm_mma<2>,
                         cudaFuncAttributeMaxDynamicSharedMemorySize, GEMM_SMEM_BYTES);
    cudaFuncSetAttribute(flash_tc,
                         cudaFuncAttributeMaxDynamicSharedMemorySize, FLASH_SMEM_BYTES);

    cudaStream_t stream = 0;

    // ---- launch 1: fused tf32 conversion pre-pass ----
    CvtArgs ca;
    ca.src[0] = (const float4*)X;     ca.dst[0] = xt;
    ca.src[1] = (const float4*)w_qa;  ca.dst[1] = wqkva;
    ca.src[2] = (const float4*)w_kva; ca.dst[2] = wqkva;
    ca.src[3] = (const float4*)w_qb;  ca.dst[3] = wqb;
    ca.src[4] = (const float4*)w_kb;  ca.dst[4] = wkv8;
    ca.src[5] = (const float4*)w_vb;  ca.dst[5] = wkv8;
    ca.src[6] = (const float4*)w_o;   ca.dst[6] = wo;
    cvt_all_kernel<<<CVT_BLOCKS, 256, 0, stream>>>(ca);

    // ---- launch 2: fused qc+ckv projection ----
    {
        dim3 grid(NQKVA / 128, TOKENS / 128);
        gemm_mma<1><<<grid, 256, GEMM_SMEM_BYTES, stream>>>(
            xt, wqkva, qc, ckv, ckvt, TOKENS, NQKVA, HID, 1.f);
    }
    // ---- launch 3: q projection (stores pre-scaled tf32 bits) ----
    {
        dim3 grid(MODEL / 128, TOKENS / 128);
        gemm_mma<2><<<grid, 256, GEMM_SMEM_BYTES, stream>>>(
            qc, wqb, q, nullptr, nullptr, TOKENS, MODEL, QRANK, SM_SCALE);
    }
    // ---- launch 4: fused k+v projection (stores tf32 bits) ----
    {
        dim3 grid(NKV / 128, TOKENS / 128);
        gemm_mma<2><<<grid, 256, GEMM_SMEM_BYTES, stream>>>(
            ckvt, wkv8, kv, nullptr, nullptr, TOKENS, NKV, KVRANK, 1.f);
    }
    // ---- launch 5: causal attention ----
    dim3 fgrid(SEQ / FQ, NHEADS, BATCH);
    flash_tc<<<fgrid, 256, FLASH_SMEM_BYTES, stream>>>(q, kv, ao);

    // ---- launch 6: output projection ----
    {
        dim3 grid(HID / 128, TOKENS / 128);
        gemm_mma<0><<<grid, 256, GEMM_SMEM_BYTES, stream>>>(
            ao, wo, attn_out, nullptr, nullptr, TOKENS, HID, MODEL, 1.f);
    }
}

// round 15
// speedup vs baseline: 1.1130x; 1.0541x over previous
#include <cuda_runtime.h>
#include <cuda_bf16.h>
#include <cstdint>
#include <cstddef>

// ---------------------------------------------------------------------------
// Problem constants
// ---------------------------------------------------------------------------
static constexpr int BATCH   = 2;
static constexpr int SEQ     = 2048;
static constexpr int HID     = 4096;
static constexpr int NHEADS  = 32;
static constexpr int HDIM    = 128;
static constexpr int QRANK   = 1536;
static constexpr int KVRANK  = 512;
static constexpr int TOKENS  = BATCH * SEQ;            // 4096
static constexpr int MODEL   = NHEADS * HDIM;          // 4096
static constexpr int NQKVA   = QRANK + KVRANK;         // 2048
static constexpr int NKV     = 2 * MODEL;              // 8192
static constexpr float SM_SCALE = 0.08838834764831845f; // 1/sqrt(128)

// ---------------------------------------------------------------------------
// Scratch (static device allocations; no cudaMalloc anywhere)
// ---------------------------------------------------------------------------
__device__ float g_qc  [(size_t)TOKENS * QRANK];       // tf32 bits
__device__ float g_q   [(size_t)TOKENS * MODEL];       // tf32 bits, pre-scaled
__device__ float g_kv  [(size_t)TOKENS * NKV];         // tf32 bits: K cols 0-4095, V cols 4096-8191
__device__ float g_ao  [(size_t)TOKENS * MODEL];       // tf32 bits
__device__ float g_xt  [(size_t)TOKENS * HID];         // tf32 bits
__device__ float g_ckvt[(size_t)TOKENS * KVRANK];      // tf32 bits
__device__ float g_wqkva[(size_t)HID   * NQKVA];       // [wqa | wkva], tf32 bits
__device__ float g_wqb [(size_t)QRANK  * MODEL];       // tf32 bits
__device__ float g_wkv8[(size_t)KVRANK * NKV];         // [wkb | wvb], tf32 bits
__device__ float g_wo  [(size_t)MODEL  * HID];         // tf32 bits

// ---------------------------------------------------------------------------
// Helpers
// ---------------------------------------------------------------------------
__device__ __forceinline__ uint32_t f2tf32(float x) {
    uint32_t r;
    asm("cvt.rna.tf32.f32 %0, %1;" : "=r"(r) : "f"(x));
    return r;
}
__device__ __forceinline__ uint32_t smem_u32(const void* p) {
    uint32_t a;
    asm("{ .reg .u64 t; cvta.to.shared.u64 t, %1; cvt.u32.u64 %0, t; }"
        : "=r"(a) : "l"(p));
    return a;
}
__device__ __forceinline__ void cp_async16(uint32_t s, const void* g) {
    asm volatile("cp.async.cg.shared.global [%0], [%1], 16;" :: "r"(s), "l"(g));
}
#define CP_COMMIT() asm volatile("cp.async.commit_group;" ::: "memory")
#define CP_WAIT1()  asm volatile("cp.async.wait_group 1;" ::: "memory")

__device__ __forceinline__ void mma_tf32(float c[4], const uint32_t a[4],
                                         const uint32_t b[2]) {
    asm volatile(
        "mma.sync.aligned.m16n8k8.row.col.f32.tf32.tf32.f32 "
        "{%0,%1,%2,%3}, {%4,%5,%6,%7}, {%8,%9}, {%0,%1,%2,%3};"
        : "+f"(c[0]), "+f"(c[1]), "+f"(c[2]), "+f"(c[3])
        : "r"(a[0]), "r"(a[1]), "r"(a[2]), "r"(a[3]), "r"(b[0]), "r"(b[1]));
}

// ---------------------------------------------------------------------------
// Fused tf32 conversion pre-pass, one launch, PURE 32-BIT index math.
// Segments 0/3/6 (X, w_qb, w_o) are straight copies (no restride).
// Segments 1/2 place [wqa | wkva] into wqkva; 4/5 place [wkb | wvb] into wkv8.
// All divisions are by compile-time constants (magic multiplies).
// ---------------------------------------------------------------------------
struct CvtArgs {
    const float4* src[7];
    float*        dst[7];
};

static constexpr int CVT_N4_0 = TOKENS * (HID / 4);      // X      4,194,304
static constexpr int CVT_N4_1 = HID * (QRANK / 4);       // w_qa   1,572,864
static constexpr int CVT_N4_2 = HID * (KVRANK / 4);      // w_kva    524,288
static constexpr int CVT_N4_3 = QRANK * (MODEL / 4);     // w_qb   1,572,864
static constexpr int CVT_N4_4 = KVRANK * (MODEL / 4);    // w_kb     524,288
static constexpr int CVT_N4_5 = KVRANK * (MODEL / 4);    // w_vb     524,288
static constexpr int CVT_N4_6 = MODEL * (HID / 4);       // w_o    4,194,304
static constexpr int CVT_CUM1 = CVT_N4_0;
static constexpr int CVT_CUM2 = CVT_CUM1 + CVT_N4_1;
static constexpr int CVT_CUM3 = CVT_CUM2 + CVT_N4_2;
static constexpr int CVT_CUM4 = CVT_CUM3 + CVT_N4_3;
static constexpr int CVT_CUM5 = CVT_CUM4 + CVT_N4_4;
static constexpr int CVT_CUM6 = CVT_CUM5 + CVT_N4_5;
static constexpr int CVT_TOTAL = CVT_CUM6 + CVT_N4_6;    // 13,107,200
static constexpr int CVT_BLOCKS = CVT_TOTAL / 256;       // 51,200 exact

__device__ __forceinline__ uint4 cvt4(float4 v) {
    return make_uint4(f2tf32(v.x), f2tf32(v.y), f2tf32(v.z), f2tf32(v.w));
}

__global__ __launch_bounds__(256) void cvt_all_kernel(CvtArgs a)
{
    int i = blockIdx.x * 256 + threadIdx.x;     // < 2^24, int exact
    if (i < CVT_CUM1) {
        // X -> xt : straight copy
        ((uint4*)a.dst[0])[i] = cvt4(a.src[0][i]);
    } else if (i < CVT_CUM2) {
        // w_qa [HID, QRANK] -> wqkva cols [0, QRANK)
        int loc = i - CVT_CUM1;
        int row = loc / (QRANK / 4);
        int c4  = (loc - row * (QRANK / 4)) * 4;
        *(uint4*)&a.dst[1][(size_t)row * NQKVA + c4] = cvt4(a.src[1][loc]);
    } else if (i < CVT_CUM3) {
        // w_kva [HID, KVRANK] -> wqkva cols [QRANK, NQKVA)
        int loc = i - CVT_CUM2;
        int row = loc / (KVRANK / 4);
        int c4  = (loc - row * (KVRANK / 4)) * 4;
        *(uint4*)&a.dst[2][(size_t)row * NQKVA + QRANK + c4] = cvt4(a.src[2][loc]);
    } else if (i < CVT_CUM4) {
        // w_qb -> wqb : straight copy
        int loc = i - CVT_CUM3;
        ((uint4*)a.dst[3])[loc] = cvt4(a.src[3][loc]);
    } else if (i < CVT_CUM5) {
        // w_kb [KVRANK, MODEL] -> wkv8 cols [0, MODEL)
        int loc = i - CVT_CUM4;
        int row = loc / (MODEL / 4);
        int c4  = (loc - row * (MODEL / 4)) * 4;
        *(uint4*)&a.dst[4][(size_t)row * NKV + c4] = cvt4(a.src[4][loc]);
    } else if (i < CVT_CUM6) {
        // w_vb [KVRANK, MODEL] -> wkv8 cols [MODEL, NKV)
        int loc = i - CVT_CUM5;
        int row = loc / (MODEL / 4);
        int c4  = (loc - row * (MODEL / 4)) * 4;
        *(uint4*)&a.dst[5][(size_t)row * NKV + MODEL + c4] = cvt4(a.src[5][loc]);
    } else {
        // w_o -> wo : straight copy
        int loc = i - CVT_CUM6;
        ((uint4*)a.dst[6])[loc] = cvt4(a.src[6][loc]);
    }
}

// ---------------------------------------------------------------------------
// mma.sync tf32 GEMM:  C[M,N] = A[M,K] @ B[K,N]  (row-major, tf32-bit inputs)
// MODE 0: exact fp32 C.  MODE 1 (QKVA): split qc/ckv epilogue.
// MODE 2: tf32 bits of acc*scale.
// Tail-issue cp.async schedule (fastest measured variant, rounds 12/14).
// ---------------------------------------------------------------------------
static constexpr int A_LD = 36;
static constexpr int B_LD = 136;
static constexpr int A_FLOATS = 128 * A_LD;
static constexpr int B_FLOATS = 32 * B_LD;
static constexpr int STAGE_FLOATS = A_FLOATS + B_FLOATS;
static constexpr int GEMM_STAGES = 3;
static constexpr int GEMM_SMEM_BYTES = GEMM_STAGES * STAGE_FLOATS * 4;  // 107,520

template <int MODE>
__global__ __launch_bounds__(256, 2) void gemm_mma(
    const float* __restrict__ A, const float* __restrict__ B,
    float* __restrict__ C, float* __restrict__ Cckv, float* __restrict__ Cckvt,
    int M, int N, int K, float scale)
{
    extern __shared__ uint32_t smu[];
    const uint32_t sbase = smem_u32(smu);

    const int tid  = threadIdx.x;
    const int wid  = tid >> 5;
    const int lane = tid & 31;
    const int warpM = wid >> 2;
    const int warpN = wid & 3;
    const int m0 = blockIdx.y * 128;
    const int n0 = blockIdx.x * 128;
    const int r  = lane >> 2;
    const int cq = lane & 3;

    const int arow = tid >> 3;
    const int ac4  = (tid & 7) << 2;
    const int brow = tid >> 5;
    const int bn4  = (tid & 31) << 2;

    float acc[4][4][4];
#pragma unroll
    for (int mi = 0; mi < 4; mi++)
#pragma unroll
        for (int nj = 0; nj < 4; nj++)
#pragma unroll
            for (int t = 0; t < 4; t++) acc[mi][nj][t] = 0.f;

    const int KT = K >> 5;

    auto issue = [&](int it) {
        const int s = it % GEMM_STAGES;
        const uint32_t as = sbase + (uint32_t)(s * STAGE_FLOATS) * 4u;
        const uint32_t bs = as + (uint32_t)A_FLOATS * 4u;
        const int k0 = it << 5;
#pragma unroll
        for (int i = 0; i < 4; i++) {
            int row = arow + i * 32;
            cp_async16(as + (uint32_t)(row * A_LD + ac4) * 4u,
                       A + (size_t)(m0 + row) * K + k0 + ac4);
        }
#pragma unroll
        for (int i = 0; i < 4; i++) {
            int row = brow + i * 8;
            cp_async16(bs + (uint32_t)(row * B_LD + bn4) * 4u,
                       B + (size_t)(k0 + row) * N + n0 + bn4);
        }
    };

    issue(0); CP_COMMIT();
    issue(1); CP_COMMIT();

    for (int it = 0; it < KT; ++it) {
        CP_WAIT1();
        __syncthreads();

        const uint32_t* as = smu + (it % GEMM_STAGES) * STAGE_FLOATS;
        const uint32_t* bs = as + A_FLOATS;
#pragma unroll
        for (int ks = 0; ks < 4; ++ks) {
            uint32_t af[4][4];
#pragma unroll
            for (int mi = 0; mi < 4; mi++) {
                int rb = (warpM * 64 + mi * 16 + r) * A_LD + ks * 8 + cq;
                af[mi][0] = as[rb];
                af[mi][1] = as[rb + 8 * A_LD];
                af[mi][2] = as[rb + 4];
                af[mi][3] = as[rb + 8 * A_LD + 4];
            }
            uint32_t bf[4][2];
#pragma unroll
            for (int nj = 0; nj < 4; nj++) {
                int bb = (ks * 8 + cq) * B_LD + warpN * 32 + nj * 8 + r;
                bf[nj][0] = bs[bb];
                bf[nj][1] = bs[bb + 4 * B_LD];
            }
#pragma unroll
            for (int mi = 0; mi < 4; mi++)
#pragma unroll
                for (int nj = 0; nj < 4; nj++)
                    mma_tf32(acc[mi][nj], af[mi], bf[nj]);
        }

        if (it + 2 < KT) issue(it + 2);
        CP_COMMIT();
    }

#pragma unroll
    for (int mi = 0; mi < 4; mi++) {
        const int row0 = m0 + warpM * 64 + mi * 16 + r;
#pragma unroll
        for (int nj = 0; nj < 4; nj++) {
            const int col = n0 + warpN * 32 + nj * 8 + 2 * cq;
            if (MODE == 1) {
                if (col < QRANK) {
                    *(uint2*)&C[(size_t)row0 * QRANK + col] =
                        make_uint2(f2tf32(acc[mi][nj][0]), f2tf32(acc[mi][nj][1]));
                    *(uint2*)&C[(size_t)(row0 + 8) * QRANK + col] =
                        make_uint2(f2tf32(acc[mi][nj][2]), f2tf32(acc[mi][nj][3]));
                } else {
                    int colr = col - QRANK;
                    size_t o0 = (size_t)row0 * KVRANK + colr;
                    size_t o1 = (size_t)(row0 + 8) * KVRANK + colr;
                    *(float2*)&Cckv[o0] = make_float2(acc[mi][nj][0], acc[mi][nj][1]);
                    *(float2*)&Cckv[o1] = make_float2(acc[mi][nj][2], acc[mi][nj][3]);
                    *(uint2*)&Cckvt[o0] =
                        make_uint2(f2tf32(acc[mi][nj][0]), f2tf32(acc[mi][nj][1]));
                    *(uint2*)&Cckvt[o1] =
                        make_uint2(f2tf32(acc[mi][nj][2]), f2tf32(acc[mi][nj][3]));
                }
            } else if (MODE == 2) {
                *(uint2*)&C[(size_t)row0 * N + col] =
                    make_uint2(f2tf32(acc[mi][nj][0] * scale),
                               f2tf32(acc[mi][nj][1] * scale));
                *(uint2*)&C[(size_t)(row0 + 8) * N + col] =
                    make_uint2(f2tf32(acc[mi][nj][2] * scale),
                               f2tf32(acc[mi][nj][3] * scale));
            } else {
                *(float2*)&C[(size_t)row0 * N + col] =
                    make_float2(acc[mi][nj][0], acc[mi][nj][1]);
                *(float2*)&C[(size_t)(row0 + 8) * N + col] =
                    make_float2(acc[mi][nj][2], acc[mi][nj][3]);
            }
        }
    }
}

// ---------------------------------------------------------------------------
// Tensor-core flash attention (causal), tf32 mma + fp32 online softmax.
// Q (pre-scaled tf32 bits) and KV (tf32 bits) loaded with plain LDG+STS raw
// uint4 copies. KV layout [tokens, 8192]: K at head*128, V at 4096+head*128.
// ---------------------------------------------------------------------------
static constexpr int FQ = 128;
static constexpr int FK = 64;
static constexpr int K_LD = 132;
static constexpr int V_LD = 136;
static constexpr int P_LD = 68;
static constexpr int KW  = 64 * K_LD;
static constexpr int VW  = 64 * V_LD;
static constexpr int PW  = 128 * P_LD;
static constexpr int QFW = 128 * 128;
static constexpr int FLASH_SMEM_BYTES = (KW + VW + PW + QFW) * 4;

__global__ __launch_bounds__(256) void flash_tc(
    const float* __restrict__ Q, const float* __restrict__ KV,
    float* __restrict__ O)
{
    extern __shared__ uint32_t fsm[];
    uint32_t* Ks = fsm;
    uint32_t* Vs = fsm + KW;
    uint32_t* Ps = fsm + KW + VW;
    uint32_t* Qf = fsm + KW + VW + PW;

    const int tid  = threadIdx.x;
    const int wq   = tid >> 5;
    const int lane = tid & 31;
    const int r    = lane >> 2;
    const int cq   = lane & 3;
    const int mtile = blockIdx.x;
    const int head  = blockIdx.y;
    const int b     = blockIdx.z;
    const int m0    = mtile * FQ;
    const size_t baseQ  = ((size_t)b * SEQ) * MODEL + (size_t)head * HDIM;
    const size_t baseKV = ((size_t)b * SEQ) * NKV   + (size_t)head * HDIM;

    // ---- stage Q: raw uint4 copies (128 rows x 32 float4 slots) ----
    for (int it = tid; it < 128 * 32; it += 256) {
        int row = it >> 5, c4 = (it & 31) << 2;
        uint4 t = *(const uint4*)&Q[baseQ + (size_t)(m0 + row) * MODEL + c4];
        *(uint4*)&fsm[row * K_LD + c4] = t;
    }
    __syncthreads();

    // ---- repack Q into fragment-ordered smem ----
#pragma unroll
    for (int ks = 0; ks < 16; ks++) {
        int rb = (wq * 16 + r) * K_LD + ks * 8 + cq;
        uint4 qv = { fsm[rb], fsm[rb + 8 * K_LD],
                     fsm[rb + 4], fsm[rb + 8 * K_LD + 4] };
        *(uint4*)&Qf[(((wq * 16 + ks) * 32) + lane) * 4] = qv;
    }
    __syncthreads();

    float of[16][4];
#pragma unroll
    for (int nj = 0; nj < 16; nj++)
#pragma unroll
        for (int t = 0; t < 4; t++) of[nj][t] = 0.f;

    float mrow0 = -1e30f, mrow1 = -1e30f, lrow0 = 0.f, lrow1 = 0.f;
    const int row0 = m0 + wq * 16 + r;
    const int row1 = row0 + 8;

    const int NT = 2 * (mtile + 1);
    for (int t = 0; t < NT; t++) {
        const int n0 = t * FK;

        // ---- load KV tile: raw uint4 copies (64 rows x 32 slots each) ----
        for (int it = tid; it < 64 * 32; it += 256) {
            int row = it >> 5, c4 = (it & 31) << 2;
            size_t g = baseKV + (size_t)(n0 + row) * NKV + c4;
            uint4 tk = *(const uint4*)&KV[g];
            uint4 tv = *(const uint4*)&KV[g + MODEL];
            *(uint4*)&Ks[row * K_LD + c4] = tk;
            *(uint4*)&Vs[row * V_LD + c4] = tv;
        }
        __syncthreads();

        float sc[8][4];
#pragma unroll
        for (int nj = 0; nj < 8; nj++)
#pragma unroll
            for (int e = 0; e < 4; e++) sc[nj][e] = 0.f;

#pragma unroll
        for (int ks = 0; ks < 16; ks++) {
            uint4 qa4 = *(const uint4*)&Qf[(((wq * 16 + ks) * 32) + lane) * 4];
            uint32_t qa[4] = { qa4.x, qa4.y, qa4.z, qa4.w };
            uint32_t bf[8][2];
#pragma unroll
            for (int nj = 0; nj < 8; nj++) {
                int ib = (nj * 8 + r) * K_LD + ks * 8 + cq;
                bf[nj][0] = Ks[ib];
                bf[nj][1] = Ks[ib + 4];
            }
#pragma unroll
            for (int nj = 0; nj < 8; nj++)
                mma_tf32(sc[nj], qa, bf[nj]);
        }

        if (n0 + FK - 1 > m0) {
#pragma unroll
            for (int nj = 0; nj < 8; nj++) {
                int kk = n0 + nj * 8 + 2 * cq;
                if (kk     > row0) sc[nj][0] = -1e30f;
                if (kk + 1 > row0) sc[nj][1] = -1e30f;
                if (kk     > row1) sc[nj][2] = -1e30f;
                if (kk + 1 > row1) sc[nj][3] = -1e30f;
            }
        }

        float tmax0 = -1e30f, tmax1 = -1e30f;
#pragma unroll
        for (int nj = 0; nj < 8; nj++) {
            tmax0 = fmaxf(tmax0, fmaxf(sc[nj][0], sc[nj][1]));
            tmax1 = fmaxf(tmax1, fmaxf(sc[nj][2], sc[nj][3]));
        }
        tmax0 = fmaxf(tmax0, __shfl_xor_sync(0xffffffffu, tmax0, 1));
        tmax0 = fmaxf(tmax0, __shfl_xor_sync(0xffffffffu, tmax0, 2));
        tmax1 = fmaxf(tmax1, __shfl_xor_sync(0xffffffffu, tmax1, 1));
        tmax1 = fmaxf(tmax1, __shfl_xor_sync(0xffffffffu, tmax1, 2));

        float nm0 = fmaxf(mrow0, tmax0);
        float nm1 = fmaxf(mrow1, tmax1);
        float c0 = __expf(mrow0 - nm0);
        float c1 = __expf(mrow1 - nm1);
        float ts0 = 0.f, ts1 = 0.f;
#pragma unroll
        for (int nj = 0; nj < 8; nj++) {
            float p0 = __expf(sc[nj][0] - nm0);
            float p1 = __expf(sc[nj][1] - nm0);
            float p2 = __expf(sc[nj][2] - nm1);
            float p3 = __expf(sc[nj][3] - nm1);
            ts0 += p0 + p1;
            ts1 += p2 + p3;
            uint2 u0 = { f2tf32(p0), f2tf32(p1) };
            uint2 u1 = { f2tf32(p2), f2tf32(p3) };
            *(uint2*)&Ps[(wq * 16 + r) * P_LD + nj * 8 + 2 * cq]     = u0;
            *(uint2*)&Ps[(wq * 16 + r + 8) * P_LD + nj * 8 + 2 * cq] = u1;
        }
        ts0 += __shfl_xor_sync(0xffffffffu, ts0, 1);
        ts0 += __shfl_xor_sync(0xffffffffu, ts0, 2);
        ts1 += __shfl_xor_sync(0xffffffffu, ts1, 1);
        ts1 += __shfl_xor_sync(0xffffffffu, ts1, 2);

        mrow0 = nm0; mrow1 = nm1;
        lrow0 = lrow0 * c0 + ts0;
        lrow1 = lrow1 * c1 + ts1;
#pragma unroll
        for (int nj = 0; nj < 16; nj++) {
            of[nj][0] *= c0; of[nj][1] *= c0;
            of[nj][2] *= c1; of[nj][3] *= c1;
        }
        __syncwarp();

#pragma unroll
        for (int ks = 0; ks < 8; ks++) {
            uint32_t ap[4];
            int rb = (wq * 16 + r) * P_LD + ks * 8 + cq;
            ap[0] = Ps[rb];
            ap[1] = Ps[rb + 8 * P_LD];
            ap[2] = Ps[rb + 4];
            ap[3] = Ps[rb + 8 * P_LD + 4];
            uint32_t bf[16][2];
#pragma unroll
            for (int nj = 0; nj < 16; nj++) {
                int ib = (ks * 8 + cq) * V_LD + nj * 8 + r;
                bf[nj][0] = Vs[ib];
                bf[nj][1] = Vs[ib + 4 * V_LD];
            }
#pragma unroll
            for (int nj = 0; nj < 16; nj++)
                mma_tf32(of[nj], ap, bf[nj]);
        }
        __syncthreads();
    }

    const float inv0 = 1.f / lrow0;
    const float inv1 = 1.f / lrow1;
#pragma unroll
    for (int nj = 0; nj < 16; nj++) {
        int col = nj * 8 + 2 * cq;
        *(uint2*)&O[baseQ + (size_t)row0 * MODEL + col] =
            make_uint2(f2tf32(of[nj][0] * inv0), f2tf32(of[nj][1] * inv0));
        *(uint2*)&O[baseQ + (size_t)row1 * MODEL + col] =
            make_uint2(f2tf32(of[nj][2] * inv1), f2tf32(of[nj][3] * inv1));
    }
}

// ---------------------------------------------------------------------------
// Launch
// ---------------------------------------------------------------------------
extern "C" void kernel_launch(void* const* d_in, const int* in_sizes, int n_in,
                              void* d_out, int out_size)
{
    (void)in_sizes; (void)n_in; (void)out_size;
    const float* X     = (const float*)d_in[0];
    const float* w_qa  = (const float*)d_in[1];
    const float* w_qb  = (const float*)d_in[2];
    const float* w_kva = (const float*)d_in[3];
    const float* w_kb  = (const float*)d_in[4];
    const float* w_vb  = (const float*)d_in[5];
    const float* w_o   = (const float*)d_in[6];

    float* attn_out = (float*)d_out;
    float* ckv      = (float*)d_out + (size_t)TOKENS * HID;

    float *qc, *q, *kv, *ao, *xt, *ckvt, *wqkva, *wqb, *wkv8, *wo;
    cudaGetSymbolAddress((void**)&qc,    g_qc);
    cudaGetSymbolAddress((void**)&q,     g_q);
    cudaGetSymbolAddress((void**)&kv,    g_kv);
    cudaGetSymbolAddress((void**)&ao,    g_ao);
    cudaGetSymbolAddress((void**)&xt,    g_xt);
    cudaGetSymbolAddress((void**)&ckvt,  g_ckvt);
    cudaGetSymbolAddress((void**)&wqkva, g_wqkva);
    cudaGetSymbolAddress((void**)&wqb,   g_wqb);
    cudaGetSymbolAddress((void**)&wkv8,  g_wkv8);
    cudaGetSymbolAddress((void**)&wo,    g_wo);

    cudaFuncSetAttribute(gemm_mma<0>,
                         cudaFuncAttributeMaxDynamicSharedMemorySize, GEMM_SMEM_BYTES);
    cudaFuncSetAttribute(gemm_mma<1>,
                         cudaFuncAttributeMaxDynamicSharedMemorySize, GEMM_SMEM_BYTES);
    cudaFuncSetAttribute(gemm_mma<2>,
                         cudaFuncAttributeMaxDynamicSharedMemorySize, GEMM_SMEM_BYTES);
    cudaFuncSetAttribute(flash_tc,
                         cudaFuncAttributeMaxDynamicSharedMemorySize, FLASH_SMEM_BYTES);

    cudaStream_t stream = 0;

    // ---- launch 1: fused tf32 conversion pre-pass (32-bit index math) ----
    CvtArgs ca;
    ca.src[0] = (const float4*)X;     ca.dst[0] = xt;
    ca.src[1] = (const float4*)w_qa;  ca.dst[1] = wqkva;
    ca.src[2] = (const float4*)w_kva; ca.dst[2] = wqkva;
    ca.src[3] = (const float4*)w_qb;  ca.dst[3] = wqb;
    ca.src[4] = (const float4*)w_kb;  ca.dst[4] = wkv8;
    ca.src[5] = (const float4*)w_vb;  ca.dst[5] = wkv8;
    ca.src[6] = (const float4*)w_o;   ca.dst[6] = wo;
    cvt_all_kernel<<<CVT_BLOCKS, 256, 0, stream>>>(ca);

    // ---- launch 2: fused qc+ckv projection ----
    {
        dim3 grid(NQKVA / 128, TOKENS / 128);
        gemm_mma<1><<<grid, 256, GEMM_SMEM_BYTES, stream>>>(
            xt, wqkva, qc, ckv, ckvt, TOKENS, NQKVA, HID, 1.f);
    }
    // ---- launch 3: q projection (stores pre-scaled tf32 bits) ----
    {
        dim3 grid(MODEL / 128, TOKENS / 128);
        gemm_mma<2><<<grid, 256, GEMM_SMEM_BYTES, stream>>>(
            qc, wqb, q, nullptr, nullptr, TOKENS, MODEL, QRANK, SM_SCALE);
    }
    // ---- launch 4: fused k+v projection (stores tf32 bits) ----
    {
        dim3 grid(NKV / 128, TOKENS / 128);
        gemm_mma<2><<<grid, 256, GEMM_SMEM_BYTES, stream>>>(
            ckvt, wkv8, kv, nullptr, nullptr, TOKENS, NKV, KVRANK, 1.f);
    }
    // ---- launch 5: causal attention ----
    dim3 fgrid(SEQ / FQ, NHEADS, BATCH);
    flash_tc<<<fgrid, 256, FLASH_SMEM_BYTES, stream>>>(q, kv, ao);

    // ---- launch 6: output projection ----
    {
        dim3 grid(HID / 128, TOKENS / 128);
        gemm_mma<0><<<grid, 256, GEMM_SMEM_BYTES, stream>>>(
            ao, wo, attn_out, nullptr, nullptr, TOKENS, HID, MODEL, 1.f);
    }
}

// round 16
// speedup vs baseline: 1.1846x; 1.0643x over previous
#include <cuda_runtime.h>
#include <cuda_bf16.h>
#include <cstdint>
#include <cstddef>

// ---------------------------------------------------------------------------
// Problem constants
// ---------------------------------------------------------------------------
static constexpr int BATCH   = 2;
static constexpr int SEQ     = 2048;
static constexpr int HID     = 4096;
static constexpr int NHEADS  = 32;
static constexpr int HDIM    = 128;
static constexpr int QRANK   = 1536;
static constexpr int KVRANK  = 512;
static constexpr int TOKENS  = BATCH * SEQ;            // 4096
static constexpr int MODEL   = NHEADS * HDIM;          // 4096
static constexpr int NQKVA   = QRANK + KVRANK;         // 2048
static constexpr int NKV     = 2 * MODEL;              // 8192
static constexpr float SM_SCALE = 0.08838834764831845f; // 1/sqrt(128)

// ---------------------------------------------------------------------------
// Scratch (static device allocations; no cudaMalloc anywhere)
// ---------------------------------------------------------------------------
__device__ float g_qc  [(size_t)TOKENS * QRANK];       // tf32 bits
__device__ float g_q   [(size_t)TOKENS * MODEL];       // tf32 bits, pre-scaled
__device__ float g_kv  [(size_t)TOKENS * NKV];         // tf32 bits
__device__ float g_ao  [(size_t)TOKENS * MODEL];       // tf32 bits
__device__ float g_xt  [(size_t)TOKENS * HID];         // tf32 bits
__device__ float g_ckvt[(size_t)TOKENS * KVRANK];      // tf32 bits
__device__ float g_wqkva[(size_t)HID   * NQKVA];       // [wqa | wkva], tf32 bits
__device__ float g_wqb [(size_t)QRANK  * MODEL];       // tf32 bits
__device__ float g_wkv8[(size_t)KVRANK * NKV];         // [wkb | wvb], tf32 bits
__device__ float g_wo  [(size_t)MODEL  * HID];         // tf32 bits

// ---------------------------------------------------------------------------
// Helpers
// ---------------------------------------------------------------------------
__device__ __forceinline__ uint32_t f2tf32(float x) {
    uint32_t r;
    asm("cvt.rna.tf32.f32 %0, %1;" : "=r"(r) : "f"(x));
    return r;
}
__device__ __forceinline__ uint32_t smem_u32(const void* p) {
    uint32_t a;
    asm("{ .reg .u64 t; cvta.to.shared.u64 t, %1; cvt.u32.u64 %0, t; }"
        : "=r"(a) : "l"(p));
    return a;
}
__device__ __forceinline__ void cp_async16(uint32_t s, const void* g) {
    asm volatile("cp.async.cg.shared.global [%0], [%1], 16;" :: "r"(s), "l"(g));
}
#define CP_COMMIT() asm volatile("cp.async.commit_group;" ::: "memory")
#define CP_WAIT1()  asm volatile("cp.async.wait_group 1;" ::: "memory")
#define CP_WAIT0()  asm volatile("cp.async.wait_group 0;" ::: "memory")

__device__ __forceinline__ void mma_tf32(float c[4], const uint32_t a[4],
                                         const uint32_t b[2]) {
    asm volatile(
        "mma.sync.aligned.m16n8k8.row.col.f32.tf32.tf32.f32 "
        "{%0,%1,%2,%3}, {%4,%5,%6,%7}, {%8,%9}, {%0,%1,%2,%3};"
        : "+f"(c[0]), "+f"(c[1]), "+f"(c[2]), "+f"(c[3])
        : "r"(a[0]), "r"(a[1]), "r"(a[2]), "r"(a[3]), "r"(b[0]), "r"(b[1]));
}

// ---------------------------------------------------------------------------
// Fused tf32 conversion pre-pass, one launch, pure 32-bit index math.
// ---------------------------------------------------------------------------
struct CvtArgs {
    const float4* src[7];
    float*        dst[7];
};

static constexpr int CVT_N4_0 = TOKENS * (HID / 4);
static constexpr int CVT_N4_1 = HID * (QRANK / 4);
static constexpr int CVT_N4_2 = HID * (KVRANK / 4);
static constexpr int CVT_N4_3 = QRANK * (MODEL / 4);
static constexpr int CVT_N4_4 = KVRANK * (MODEL / 4);
static constexpr int CVT_N4_5 = KVRANK * (MODEL / 4);
static constexpr int CVT_N4_6 = MODEL * (HID / 4);
static constexpr int CVT_CUM1 = CVT_N4_0;
static constexpr int CVT_CUM2 = CVT_CUM1 + CVT_N4_1;
static constexpr int CVT_CUM3 = CVT_CUM2 + CVT_N4_2;
static constexpr int CVT_CUM4 = CVT_CUM3 + CVT_N4_3;
static constexpr int CVT_CUM5 = CVT_CUM4 + CVT_N4_4;
static constexpr int CVT_CUM6 = CVT_CUM5 + CVT_N4_5;
static constexpr int CVT_TOTAL = CVT_CUM6 + CVT_N4_6;
static constexpr int CVT_BLOCKS = CVT_TOTAL / 256;

__device__ __forceinline__ uint4 cvt4(float4 v) {
    return make_uint4(f2tf32(v.x), f2tf32(v.y), f2tf32(v.z), f2tf32(v.w));
}

__global__ __launch_bounds__(256) void cvt_all_kernel(CvtArgs a)
{
    int i = blockIdx.x * 256 + threadIdx.x;
    if (i < CVT_CUM1) {
        ((uint4*)a.dst[0])[i] = cvt4(a.src[0][i]);
    } else if (i < CVT_CUM2) {
        int loc = i - CVT_CUM1;
        int row = loc / (QRANK / 4);
        int c4  = (loc - row * (QRANK / 4)) * 4;
        *(uint4*)&a.dst[1][(size_t)row * NQKVA + c4] = cvt4(a.src[1][loc]);
    } else if (i < CVT_CUM3) {
        int loc = i - CVT_CUM2;
        int row = loc / (KVRANK / 4);
        int c4  = (loc - row * (KVRANK / 4)) * 4;
        *(uint4*)&a.dst[2][(size_t)row * NQKVA + QRANK + c4] = cvt4(a.src[2][loc]);
    } else if (i < CVT_CUM4) {
        int loc = i - CVT_CUM3;
        ((uint4*)a.dst[3])[loc] = cvt4(a.src[3][loc]);
    } else if (i < CVT_CUM5) {
        int loc = i - CVT_CUM4;
        int row = loc / (MODEL / 4);
        int c4  = (loc - row * (MODEL / 4)) * 4;
        *(uint4*)&a.dst[4][(size_t)row * NKV + c4] = cvt4(a.src[4][loc]);
    } else if (i < CVT_CUM6) {
        int loc = i - CVT_CUM5;
        int row = loc / (MODEL / 4);
        int c4  = (loc - row * (MODEL / 4)) * 4;
        *(uint4*)&a.dst[5][(size_t)row * NKV + MODEL + c4] = cvt4(a.src[5][loc]);
    } else {
        int loc = i - CVT_CUM6;
        ((uint4*)a.dst[6])[loc] = cvt4(a.src[6][loc]);
    }
}

// ---------------------------------------------------------------------------
// mma.sync tf32 GEMM (verified rounds 12/14/15 version, tail-issue schedule)
// ---------------------------------------------------------------------------
static constexpr int A_LD = 36;
static constexpr int B_LD = 136;
static constexpr int A_FLOATS = 128 * A_LD;
static constexpr int B_FLOATS = 32 * B_LD;
static constexpr int STAGE_FLOATS = A_FLOATS + B_FLOATS;
static constexpr int GEMM_STAGES = 3;
static constexpr int GEMM_SMEM_BYTES = GEMM_STAGES * STAGE_FLOATS * 4;  // 107,520

template <int MODE>
__global__ __launch_bounds__(256, 2) void gemm_mma(
    const float* __restrict__ A, const float* __restrict__ B,
    float* __restrict__ C, float* __restrict__ Cckv, float* __restrict__ Cckvt,
    int M, int N, int K, float scale)
{
    extern __shared__ uint32_t smu[];
    const uint32_t sbase = smem_u32(smu);

    const int tid  = threadIdx.x;
    const int wid  = tid >> 5;
    const int lane = tid & 31;
    const int warpM = wid >> 2;
    const int warpN = wid & 3;
    const int m0 = blockIdx.y * 128;
    const int n0 = blockIdx.x * 128;
    const int r  = lane >> 2;
    const int cq = lane & 3;

    const int arow = tid >> 3;
    const int ac4  = (tid & 7) << 2;
    const int brow = tid >> 5;
    const int bn4  = (tid & 31) << 2;

    float acc[4][4][4];
#pragma unroll
    for (int mi = 0; mi < 4; mi++)
#pragma unroll
        for (int nj = 0; nj < 4; nj++)
#pragma unroll
            for (int t = 0; t < 4; t++) acc[mi][nj][t] = 0.f;

    const int KT = K >> 5;

    auto issue = [&](int it) {
        const int s = it % GEMM_STAGES;
        const uint32_t as = sbase + (uint32_t)(s * STAGE_FLOATS) * 4u;
        const uint32_t bs = as + (uint32_t)A_FLOATS * 4u;
        const int k0 = it << 5;
#pragma unroll
        for (int i = 0; i < 4; i++) {
            int row = arow + i * 32;
            cp_async16(as + (uint32_t)(row * A_LD + ac4) * 4u,
                       A + (size_t)(m0 + row) * K + k0 + ac4);
        }
#pragma unroll
        for (int i = 0; i < 4; i++) {
            int row = brow + i * 8;
            cp_async16(bs + (uint32_t)(row * B_LD + bn4) * 4u,
                       B + (size_t)(k0 + row) * N + n0 + bn4);
        }
    };

    issue(0); CP_COMMIT();
    issue(1); CP_COMMIT();

    for (int it = 0; it < KT; ++it) {
        CP_WAIT1();
        __syncthreads();

        const uint32_t* as = smu + (it % GEMM_STAGES) * STAGE_FLOATS;
        const uint32_t* bs = as + A_FLOATS;
#pragma unroll
        for (int ks = 0; ks < 4; ++ks) {
            uint32_t af[4][4];
#pragma unroll
            for (int mi = 0; mi < 4; mi++) {
                int rb = (warpM * 64 + mi * 16 + r) * A_LD + ks * 8 + cq;
                af[mi][0] = as[rb];
                af[mi][1] = as[rb + 8 * A_LD];
                af[mi][2] = as[rb + 4];
                af[mi][3] = as[rb + 8 * A_LD + 4];
            }
            uint32_t bf[4][2];
#pragma unroll
            for (int nj = 0; nj < 4; nj++) {
                int bb = (ks * 8 + cq) * B_LD + warpN * 32 + nj * 8 + r;
                bf[nj][0] = bs[bb];
                bf[nj][1] = bs[bb + 4 * B_LD];
            }
#pragma unroll
            for (int mi = 0; mi < 4; mi++)
#pragma unroll
                for (int nj = 0; nj < 4; nj++)
                    mma_tf32(acc[mi][nj], af[mi], bf[nj]);
        }

        if (it + 2 < KT) issue(it + 2);
        CP_COMMIT();
    }

#pragma unroll
    for (int mi = 0; mi < 4; mi++) {
        const int row0 = m0 + warpM * 64 + mi * 16 + r;
#pragma unroll
        for (int nj = 0; nj < 4; nj++) {
            const int col = n0 + warpN * 32 + nj * 8 + 2 * cq;
            if (MODE == 1) {
                if (col < QRANK) {
                    *(uint2*)&C[(size_t)row0 * QRANK + col] =
                        make_uint2(f2tf32(acc[mi][nj][0]), f2tf32(acc[mi][nj][1]));
                    *(uint2*)&C[(size_t)(row0 + 8) * QRANK + col] =
                        make_uint2(f2tf32(acc[mi][nj][2]), f2tf32(acc[mi][nj][3]));
                } else {
                    int colr = col - QRANK;
                    size_t o0 = (size_t)row0 * KVRANK + colr;
                    size_t o1 = (size_t)(row0 + 8) * KVRANK + colr;
                    *(float2*)&Cckv[o0] = make_float2(acc[mi][nj][0], acc[mi][nj][1]);
                    *(float2*)&Cckv[o1] = make_float2(acc[mi][nj][2], acc[mi][nj][3]);
                    *(uint2*)&Cckvt[o0] =
                        make_uint2(f2tf32(acc[mi][nj][0]), f2tf32(acc[mi][nj][1]));
                    *(uint2*)&Cckvt[o1] =
                        make_uint2(f2tf32(acc[mi][nj][2]), f2tf32(acc[mi][nj][3]));
                }
            } else if (MODE == 2) {
                *(uint2*)&C[(size_t)row0 * N + col] =
                    make_uint2(f2tf32(acc[mi][nj][0] * scale),
                               f2tf32(acc[mi][nj][1] * scale));
                *(uint2*)&C[(size_t)(row0 + 8) * N + col] =
                    make_uint2(f2tf32(acc[mi][nj][2] * scale),
                               f2tf32(acc[mi][nj][3] * scale));
            } else {
                *(float2*)&C[(size_t)row0 * N + col] =
                    make_float2(acc[mi][nj][0], acc[mi][nj][1]);
                *(float2*)&C[(size_t)(row0 + 8) * N + col] =
                    make_float2(acc[mi][nj][2], acc[mi][nj][3]);
            }
        }
    }
}

// ---------------------------------------------------------------------------
// Tensor-core flash attention (causal), tf32 mma + fp32 online softmax.
// v6: 2-stage cp.async KV pipeline. Q fragments in registers. Per iter:
//   wait(tile t) -> barrier -> QK+softmax -> issue(t+1) -> PV
// Tile t+1's load overlaps the PV phase. One barrier per iteration.
// ---------------------------------------------------------------------------
static constexpr int FQ = 128;
static constexpr int FK = 64;
static constexpr int K_LD = 132;
static constexpr int V_LD = 136;
static constexpr int P_LD = 68;
static constexpr int KW  = 64 * K_LD;              // 8448
static constexpr int VW  = 64 * V_LD;              // 8704
static constexpr int STW = KW + VW;                // 17152 per stage
static constexpr int PW  = 128 * P_LD;             // 8704
static constexpr int FLASH_SMEM_BYTES = (2 * STW + PW) * 4;   // 172,032

__global__ __launch_bounds__(256) void flash_tc(
    const float* __restrict__ Q, const float* __restrict__ KV,
    float* __restrict__ O)
{
    extern __shared__ uint32_t fsm[];
    uint32_t* Ps = fsm + 2 * STW;
    const uint32_t sbase = smem_u32(fsm);

    const int tid  = threadIdx.x;
    const int wq   = tid >> 5;
    const int lane = tid & 31;
    const int r    = lane >> 2;
    const int cq   = lane & 3;
    const int mtile = blockIdx.x;
    const int head  = blockIdx.y;
    const int b     = blockIdx.z;
    const int m0    = mtile * FQ;
    const size_t baseQ  = ((size_t)b * SEQ) * MODEL + (size_t)head * HDIM;
    const size_t baseKV = ((size_t)b * SEQ) * NKV   + (size_t)head * HDIM;

    // ---- stage Q (pre-scaled tf32 bits) through stage-0 area ----
    for (int it = tid; it < 128 * 32; it += 256) {
        int row = it >> 5, c4 = (it & 31) << 2;
        uint4 t = *(const uint4*)&Q[baseQ + (size_t)(m0 + row) * MODEL + c4];
        *(uint4*)&fsm[row * K_LD + c4] = t;
    }
    __syncthreads();

    // ---- Q fragments -> registers ----
    uint32_t qf[16][4];
#pragma unroll
    for (int ks = 0; ks < 16; ks++) {
        int rb = (wq * 16 + r) * K_LD + ks * 8 + cq;
        qf[ks][0] = fsm[rb];
        qf[ks][1] = fsm[rb + 8 * K_LD];
        qf[ks][2] = fsm[rb + 4];
        qf[ks][3] = fsm[rb + 8 * K_LD + 4];
    }
    __syncthreads();   // stage-0 area free for KV tile 0

    // ---- cp.async issue for one KV tile into stage s ----
    auto issue_kv = [&](int t, int s) {
        const uint32_t kb = sbase + (uint32_t)(s * STW) * 4u;
        const uint32_t vb = kb + (uint32_t)KW * 4u;
        const int n0 = t * FK;
#pragma unroll
        for (int i = 0; i < 8; i++) {
            int slot = tid + i * 256;
            int row = slot >> 5, c4 = (slot & 31) << 2;
            size_t g = baseKV + (size_t)(n0 + row) * NKV + c4;
            cp_async16(kb + (uint32_t)(row * K_LD + c4) * 4u, KV + g);
            cp_async16(vb + (uint32_t)(row * V_LD + c4) * 4u, KV + g + MODEL);
        }
    };

    float of[16][4];
#pragma unroll
    for (int nj = 0; nj < 16; nj++)
#pragma unroll
        for (int t = 0; t < 4; t++) of[nj][t] = 0.f;

    float mrow0 = -1e30f, mrow1 = -1e30f, lrow0 = 0.f, lrow1 = 0.f;
    const int row0 = m0 + wq * 16 + r;
    const int row1 = row0 + 8;

    const int NT = 2 * (mtile + 1);

    issue_kv(0, 0);
    CP_COMMIT();

    for (int t = 0; t < NT; t++) {
        const int n0 = t * FK;
        const int s  = t & 1;
        const uint32_t* Ks = fsm + s * STW;
        const uint32_t* Vs = Ks + KW;

        CP_WAIT0();        // tile t arrived (single group outstanding)
        __syncthreads();   // all threads see it; all finished PV(t-1)

        // ---- S = Q K^T ----
        float sc[8][4];
#pragma unroll
        for (int nj = 0; nj < 8; nj++)
#pragma unroll
            for (int e = 0; e < 4; e++) sc[nj][e] = 0.f;

#pragma unroll
        for (int ks = 0; ks < 16; ks++) {
            uint32_t bf[8][2];
#pragma unroll
            for (int nj = 0; nj < 8; nj++) {
                int ib = (nj * 8 + r) * K_LD + ks * 8 + cq;
                bf[nj][0] = Ks[ib];
                bf[nj][1] = Ks[ib + 4];
            }
#pragma unroll
            for (int nj = 0; nj < 8; nj++)
                mma_tf32(sc[nj], qf[ks], bf[nj]);
        }

        // ---- causal mask (diagonal tiles only) ----
        if (n0 + FK - 1 > m0) {
#pragma unroll
            for (int nj = 0; nj < 8; nj++) {
                int kk = n0 + nj * 8 + 2 * cq;
                if (kk     > row0) sc[nj][0] = -1e30f;
                if (kk + 1 > row0) sc[nj][1] = -1e30f;
                if (kk     > row1) sc[nj][2] = -1e30f;
                if (kk + 1 > row1) sc[nj][3] = -1e30f;
            }
        }

        // ---- online softmax (warp-local rows; quad shuffles) ----
        float tmax0 = -1e30f, tmax1 = -1e30f;
#pragma unroll
        for (int nj = 0; nj < 8; nj++) {
            tmax0 = fmaxf(tmax0, fmaxf(sc[nj][0], sc[nj][1]));
            tmax1 = fmaxf(tmax1, fmaxf(sc[nj][2], sc[nj][3]));
        }
        tmax0 = fmaxf(tmax0, __shfl_xor_sync(0xffffffffu, tmax0, 1));
        tmax0 = fmaxf(tmax0, __shfl_xor_sync(0xffffffffu, tmax0, 2));
        tmax1 = fmaxf(tmax1, __shfl_xor_sync(0xffffffffu, tmax1, 1));
        tmax1 = fmaxf(tmax1, __shfl_xor_sync(0xffffffffu, tmax1, 2));

        float nm0 = fmaxf(mrow0, tmax0);
        float nm1 = fmaxf(mrow1, tmax1);
        float c0 = __expf(mrow0 - nm0);
        float c1 = __expf(mrow1 - nm1);
        float ts0 = 0.f, ts1 = 0.f;
#pragma unroll
        for (int nj = 0; nj < 8; nj++) {
            float p0 = __expf(sc[nj][0] - nm0);
            float p1 = __expf(sc[nj][1] - nm0);
            float p2 = __expf(sc[nj][2] - nm1);
            float p3 = __expf(sc[nj][3] - nm1);
            ts0 += p0 + p1;
            ts1 += p2 + p3;
            uint2 u0 = { f2tf32(p0), f2tf32(p1) };
            uint2 u1 = { f2tf32(p2), f2tf32(p3) };
            *(uint2*)&Ps[(wq * 16 + r) * P_LD + nj * 8 + 2 * cq]     = u0;
            *(uint2*)&Ps[(wq * 16 + r + 8) * P_LD + nj * 8 + 2 * cq] = u1;
        }
        ts0 += __shfl_xor_sync(0xffffffffu, ts0, 1);
        ts0 += __shfl_xor_sync(0xffffffffu, ts0, 2);
        ts1 += __shfl_xor_sync(0xffffffffu, ts1, 1);
        ts1 += __shfl_xor_sync(0xffffffffu, ts1, 2);

        mrow0 = nm0; mrow1 = nm1;
        lrow0 = lrow0 * c0 + ts0;
        lrow1 = lrow1 * c1 + ts1;
#pragma unroll
        for (int nj = 0; nj < 16; nj++) {
            of[nj][0] *= c0; of[nj][1] *= c0;
            of[nj][2] *= c1; of[nj][3] *= c1;
        }

        // ---- issue KV tile t+1 (overlaps the PV phase) ----
        if (t + 1 < NT) issue_kv(t + 1, s ^ 1);
        CP_COMMIT();

        __syncwarp();   // P visible within warp

        // ---- O += P V ----
#pragma unroll
        for (int ks = 0; ks < 8; ks++) {
            uint32_t ap[4];
            int rb = (wq * 16 + r) * P_LD + ks * 8 + cq;
            ap[0] = Ps[rb];
            ap[1] = Ps[rb + 8 * P_LD];
            ap[2] = Ps[rb + 4];
            ap[3] = Ps[rb + 8 * P_LD + 4];
            uint32_t bf[16][2];
#pragma unroll
            for (int nj = 0; nj < 16; nj++) {
                int ib = (ks * 8 + cq) * V_LD + nj * 8 + r;
                bf[nj][0] = Vs[ib];
                bf[nj][1] = Vs[ib + 4 * V_LD];
            }
#pragma unroll
            for (int nj = 0; nj < 16; nj++)
                mma_tf32(of[nj], ap, bf[nj]);
        }
        // no trailing barrier: next iteration's wait+barrier orders stage reuse
    }

    const float inv0 = 1.f / lrow0;
    const float inv1 = 1.f / lrow1;
#pragma unroll
    for (int nj = 0; nj < 16; nj++) {
        int col = nj * 8 + 2 * cq;
        *(uint2*)&O[baseQ + (size_t)row0 * MODEL + col] =
            make_uint2(f2tf32(of[nj][0] * inv0), f2tf32(of[nj][1] * inv0));
        *(uint2*)&O[baseQ + (size_t)row1 * MODEL + col] =
            make_uint2(f2tf32(of[nj][2] * inv1), f2tf32(of[nj][3] * inv1));
    }
}

// ---------------------------------------------------------------------------
// Launch
// ---------------------------------------------------------------------------
extern "C" void kernel_launch(void* const* d_in, const int* in_sizes, int n_in,
                              void* d_out, int out_size)
{
    (void)in_sizes; (void)n_in; (void)out_size;
    const float* X     = (const float*)d_in[0];
    const float* w_qa  = (const float*)d_in[1];
    const float* w_qb  = (const float*)d_in[2];
    const float* w_kva = (const float*)d_in[3];
    const float* w_kb  = (const float*)d_in[4];
    const float* w_vb  = (const float*)d_in[5];
    const float* w_o   = (const float*)d_in[6];

    float* attn_out = (float*)d_out;
    float* ckv      = (float*)d_out + (size_t)TOKENS * HID;

    float *qc, *q, *kv, *ao, *xt, *ckvt, *wqkva, *wqb, *wkv8, *wo;
    cudaGetSymbolAddress((void**)&qc,    g_qc);
    cudaGetSymbolAddress((void**)&q,     g_q);
    cudaGetSymbolAddress((void**)&kv,    g_kv);
    cudaGetSymbolAddress((void**)&ao,    g_ao);
    cudaGetSymbolAddress((void**)&xt,    g_xt);
    cudaGetSymbolAddress((void**)&ckvt,  g_ckvt);
    cudaGetSymbolAddress((void**)&wqkva, g_wqkva);
    cudaGetSymbolAddress((void**)&wqb,   g_wqb);
    cudaGetSymbolAddress((void**)&wkv8,  g_wkv8);
    cudaGetSymbolAddress((void**)&wo,    g_wo);

    cudaFuncSetAttribute(gemm_mma<0>,
                         cudaFuncAttributeMaxDynamicSharedMemorySize, GEMM_SMEM_BYTES);
    cudaFuncSetAttribute(gemm_mma<1>,
                         cudaFuncAttributeMaxDynamicSharedMemorySize, GEMM_SMEM_BYTES);
    cudaFuncSetAttribute(gemm_mma<2>,
                         cudaFuncAttributeMaxDynamicSharedMemorySize, GEMM_SMEM_BYTES);
    cudaFuncSetAttribute(flash_tc,
                         cudaFuncAttributeMaxDynamicSharedMemorySize, FLASH_SMEM_BYTES);

    cudaStream_t stream = 0;

    // ---- launch 1: fused tf32 conversion pre-pass ----
    CvtArgs ca;
    ca.src[0] = (const float4*)X;     ca.dst[0] = xt;
    ca.src[1] = (const float4*)w_qa;  ca.dst[1] = wqkva;
    ca.src[2] = (const float4*)w_kva; ca.dst[2] = wqkva;
    ca.src[3] = (const float4*)w_qb;  ca.dst[3] = wqb;
    ca.src[4] = (const float4*)w_kb;  ca.dst[4] = wkv8;
    ca.src[5] = (const float4*)w_vb;  ca.dst[5] = wkv8;
    ca.src[6] = (const float4*)w_o;   ca.dst[6] = wo;
    cvt_all_kernel<<<CVT_BLOCKS, 256, 0, stream>>>(ca);

    // ---- launch 2: fused qc+ckv projection ----
    {
        dim3 grid(NQKVA / 128, TOKENS / 128);
        gemm_mma<1><<<grid, 256, GEMM_SMEM_BYTES, stream>>>(
            xt, wqkva, qc, ckv, ckvt, TOKENS, NQKVA, HID, 1.f);
    }
    // ---- launch 3: q projection (stores pre-scaled tf32 bits) ----
    {
        dim3 grid(MODEL / 128, TOKENS / 128);
        gemm_mma<2><<<grid, 256, GEMM_SMEM_BYTES, stream>>>(
            qc, wqb, q, nullptr, nullptr, TOKENS, MODEL, QRANK, SM_SCALE);
    }
    // ---- launch 4: fused k+v projection (stores tf32 bits) ----
    {
        dim3 grid(NKV / 128, TOKENS / 128);
        gemm_mma<2><<<grid, 256, GEMM_SMEM_BYTES, stream>>>(
            ckvt, wkv8, kv, nullptr, nullptr, TOKENS, NKV, KVRANK, 1.f);
    }
    // ---- launch 5: causal attention (2-stage cp.async pipeline) ----
    dim3 fgrid(SEQ / FQ, NHEADS, BATCH);
    flash_tc<<<fgrid, 256, FLASH_SMEM_BYTES, stream>>>(q, kv, ao);

    // ---- launch 6: output projection ----
    {
        dim3 grid(HID / 128, TOKENS / 128);
        gemm_mma<0><<<grid, 256, GEMM_SMEM_BYTES, stream>>>(
            ao, wo, attn_out, nullptr, nullptr, TOKENS, HID, MODEL, 1.f);
    }
}